// round 13
// baseline (speedup 1.0000x reference)
#include <cuda_runtime.h>
#include <cuda_bf16.h>
#include <math.h>
#include <cstdint>

// Problem constants (fixed shapes from reference)
#define B_  4
#define T_  2048
#define C_  1024
#define H_  16
#define HD_ 64
#define M_ROWS (B_ * T_)          // 8192
#define QKV_N  (3 * C_)           // 3072

// -------- scratch (device globals; no allocation allowed) --------
// g_q/g_k stored with k-permutation p(j)=((j&3)<<1)|(j>>2) within each 8-block
// of head dim (QK dot products invariant; lets flash load frag pairs as .64).
__device__ float    g_qkv[(size_t)M_ROWS * QKV_N];     // fp32 (B*T, 3C)
__device__ uint32_t g_q[(size_t)B_ * H_ * T_ * HD_];   // tf32 bits, roped, *0.125*log2e, permuted
__device__ uint32_t g_k[(size_t)B_ * H_ * T_ * HD_];   // tf32 bits, roped, permuted
__device__ uint32_t g_v[(size_t)B_ * H_ * T_ * HD_];   // tf32 bits (natural)
__device__ uint32_t g_y[(size_t)M_ROWS * C_];          // tf32 bits (B, T, C)
__device__ uint32_t g_xt[(size_t)M_ROWS * C_];         // tf32(x)
__device__ uint32_t g_wat[(size_t)QKV_N * C_];         // tf32(w_attn)
__device__ uint32_t g_wpt[(size_t)C_ * C_];            // tf32(w_proj)
__device__ float2   g_rt[(size_t)T_ * 32];             // rope cos/sin table

// ---- tf32 / mma / cp.async helpers ----
__device__ __forceinline__ uint32_t f2tf32(float x) {
    uint32_t r; asm("cvt.rna.tf32.f32 %0, %1;" : "=r"(r) : "f"(x)); return r;
}
__device__ __forceinline__ float ex2f(float x) {
    float r; asm("ex2.approx.ftz.f32 %0, %1;" : "=f"(r) : "f"(x)); return r;
}
__device__ __forceinline__ void mma16n8k8(float c[4], const uint32_t a[4], const uint32_t b[2]) {
    asm volatile(
        "mma.sync.aligned.m16n8k8.row.col.f32.tf32.tf32.f32 "
        "{%0,%1,%2,%3}, {%4,%5,%6,%7}, {%8,%9}, {%0,%1,%2,%3};"
        : "+f"(c[0]), "+f"(c[1]), "+f"(c[2]), "+f"(c[3])
        : "r"(a[0]), "r"(a[1]), "r"(a[2]), "r"(a[3]), "r"(b[0]), "r"(b[1]));
}
__device__ __forceinline__ uint32_t smem_u32(const void* p) {
    uint32_t a;
    asm("{ .reg .u64 t; cvta.to.shared.u64 t, %1; cvt.u32.u64 %0, t; }" : "=r"(a) : "l"(p));
    return a;
}
__device__ __forceinline__ void cp16(uint32_t dst, const void* src) {
    asm volatile("cp.async.cg.shared.global [%0], [%1], 16;" :: "r"(dst), "l"(src));
}
#define CP_COMMIT() asm volatile("cp.async.commit_group;" ::: "memory")
#define CP_WAIT1()  asm volatile("cp.async.wait_group 1;" ::: "memory")
#define CP_WAIT0()  asm volatile("cp.async.wait_group 0;" ::: "memory")

// ============================================================================
// input converter: fp32 -> tf32 bits
// ============================================================================
__global__ __launch_bounds__(256) void to_tf32(const float* __restrict__ in,
                                               uint32_t* __restrict__ out, int n)
{
    int i = (blockIdx.x * blockDim.x + threadIdx.x) * 4;
    if (i < n) {
        float4 v = *(const float4*)(in + i);
        *(uint4*)(out + i) = make_uint4(f2tf32(v.x), f2tf32(v.y), f2tf32(v.z), f2tf32(v.w));
    }
}

// ============================================================================
// Tensor-core TF32 GEMM (NT) — unchanged from Round 10/11 passing version.
// ============================================================================
#define GEMM_SMEM (24576 * 4)    // 3 stages x (A 4096 + B 4096) words = 96KB

__global__ void __launch_bounds__(256, 2) gemm_tc(
    const uint32_t* __restrict__ A, const uint32_t* __restrict__ Bm,
    float* __restrict__ C, int M, int N, int K)
{
    extern __shared__ uint32_t sm[];
    const uint32_t sbase = smem_u32(sm);

    const int tid  = threadIdx.x;
    const int lane = tid & 31;
    const int wid  = tid >> 5;
    const int wm = wid & 1;
    const int wn = wid >> 1;
    const int g = lane >> 2;
    const int t = lane & 3;
    const int bm = blockIdx.y * 128;
    const int bn = blockIdx.x * 128;

    const int lrow = tid >> 3;       // 0..31 (+p*32)
    const int lu   = tid & 7;        // 16B unit

    float acc[4][4][4];
#pragma unroll
    for (int mt = 0; mt < 4; ++mt)
#pragma unroll
        for (int nt = 0; nt < 4; ++nt)
#pragma unroll
            for (int q = 0; q < 4; ++q) acc[mt][nt][q] = 0.0f;

    auto cp_tile = [&](int k0, int s) {
#pragma unroll
        for (int p = 0; p < 4; ++p) {
            int row = lrow + p * 32;
            int u = lu ^ (row & 7);
            cp16(sbase + (uint32_t)(s * 4096 + row * 32 + u * 4) * 4,
                 A + (size_t)(bm + row) * K + k0 + lu * 4);
            cp16(sbase + (uint32_t)(12288 + s * 4096 + row * 32 + u * 4) * 4,
                 Bm + (size_t)(bn + row) * K + k0 + lu * 4);
        }
    };

    const int nk = K >> 5;
    cp_tile(0, 0); CP_COMMIT();
    cp_tile(32, 1); CP_COMMIT();

    for (int kt = 0; kt < nk; ++kt) {
        if (kt + 1 < nk) CP_WAIT1(); else CP_WAIT0();
        __syncthreads();

        const int cs = kt % 3;
        const uint32_t* Asb = sm + cs * 4096;
        const uint32_t* Bsb = sm + 12288 + cs * 4096;

#pragma unroll
        for (int c8 = 0; c8 < 4; ++c8) {
            const int u0 = (2 * c8) ^ g;
            const int u1 = u0 ^ 1;

            uint32_t af[4][4];
#pragma unroll
            for (int mt = 0; mt < 4; ++mt) {
                const int r0 = wm * 64 + mt * 16 + g;
                af[mt][0] = Asb[r0 * 32 + u0 * 4 + t];
                af[mt][1] = Asb[(r0 + 8) * 32 + u0 * 4 + t];
                af[mt][2] = Asb[r0 * 32 + u1 * 4 + t];
                af[mt][3] = Asb[(r0 + 8) * 32 + u1 * 4 + t];
            }
            uint32_t bf[4][2];
#pragma unroll
            for (int nt = 0; nt < 4; ++nt) {
                const int n0 = wn * 32 + nt * 8 + g;
                bf[nt][0] = Bsb[n0 * 32 + u0 * 4 + t];
                bf[nt][1] = Bsb[n0 * 32 + u1 * 4 + t];
            }
#pragma unroll
            for (int mt = 0; mt < 4; ++mt)
#pragma unroll
                for (int nt = 0; nt < 4; ++nt)
                    mma16n8k8(acc[mt][nt], af[mt], bf[nt]);
        }

        if (kt + 2 < nk) {
            cp_tile((kt + 2) << 5, (kt + 2) % 3);
            CP_COMMIT();
        }
    }

#pragma unroll
    for (int mt = 0; mt < 4; ++mt) {
        const int row = bm + wm * 64 + mt * 16 + g;
#pragma unroll
        for (int nt = 0; nt < 4; ++nt) {
            const int col = bn + wn * 32 + nt * 8 + 2 * t;
            *(float2*)(C + (size_t)row * N + col)       = make_float2(acc[mt][nt][0], acc[mt][nt][1]);
            *(float2*)(C + (size_t)(row + 8) * N + col) = make_float2(acc[mt][nt][2], acc[mt][nt][3]);
        }
    }
}

// ============================================================================
// RoPE table: cos/sin for (t, i) computed once per launch (fp64 accurate)
// ============================================================================
__global__ __launch_bounds__(256) void rope_tab()
{
    int idx = blockIdx.x * blockDim.x + threadIdx.x;
    if (idx >= T_ * 32) return;
    int i = idx & 31;
    int t = idx >> 5;
    double inv = exp2(-(double)i * (13.287712379549449595 / 32.0)); // 10000^(-i/32)
    double ds, dc;
    sincos((double)t * inv, &ds, &dc);
    g_rt[idx] = make_float2((float)dc, (float)ds);
}

// ============================================================================
// RoPE + rearrange: qkv (fp32) -> Q/K/V tf32 bits. Q scaled by 0.125*log2(e).
// Q/K written with the k-permutation (same scalar-store count as before).
// ============================================================================
__global__ __launch_bounds__(256) void rope_rearrange(const float* __restrict__ qkv)
{
    int idx = blockIdx.x * blockDim.x + threadIdx.x;
    if (idx >= B_ * T_ * H_ * (HD_ / 2)) return;

    int i = idx & 31;               // pair index 0..31
    int h = (idx >> 5) & 15;
    int t = (idx >> 9) & 2047;
    int b = idx >> 20;

    const float* src = qkv + (size_t)(b * T_ + t) * QKV_N + h * HD_ + 2 * i;

    float2 cs = g_rt[t * 32 + i];
    float c = cs.x, s = cs.y;

    float q0 = src[0],       q1 = src[1];
    float k0 = src[C_],      k1 = src[C_ + 1];
    float2 v2 = *(const float2*)(src + 2 * C_);

    const int d  = 2 * i;
    const int base = d & ~7;
    const int j0 = d & 7;                       // even
    const int p0 = ((j0 & 3) << 1) | (j0 >> 2); // permuted slot for j0
    const int j1 = j0 + 1;
    const int p1 = ((j1 & 3) << 1) | (j1 >> 2);

    size_t hdr = ((size_t)(b * H_ + h) * T_ + t) * HD_;
    const float qs = 0.125f * 1.44269504088896340736f;  // 1/sqrt(64) * log2(e)
    g_q[hdr + base + p0] = f2tf32((q0 * c - q1 * s) * qs);
    g_q[hdr + base + p1] = f2tf32((q0 * s + q1 * c) * qs);
    g_k[hdr + base + p0] = f2tf32(k0 * c - k1 * s);
    g_k[hdr + base + p1] = f2tf32(k0 * s + k1 * c);
    g_v[hdr + d]     = f2tf32(v2.x);
    g_v[hdr + d + 1] = f2tf32(v2.y);
}

// ============================================================================
// Tensor-core flash attention v7: Bq=128, Bk=64, hd=64. 256 threads (8 warps),
// warp = 16 q-rows. Q frags via LDG.64 pairs, K frags via LDS.64 pairs
// (k-permuted layout). K/V 2-stage cp.async ring, single sync per tile,
// prefetch after sync. P transpose via shfl. exp2 softmax, deferred l-sum.
// smem 70KB -> 2 CTAs/SM.
// ============================================================================
#define FA_KSTR 68
#define FA_VSTR 72
#define FA_KSZ  (64 * FA_KSTR)                    // 4352 words
#define FA_VSZ  (64 * FA_VSTR)                    // 4608 words
#define FA_STG  (FA_KSZ + FA_VSZ)                 // 8960 words per stage
#define FLASH_SMEM (2 * FA_STG * 4)               // 71680 bytes

__global__ void __launch_bounds__(256, 2) flash_tc()
{
    extern __shared__ uint32_t fsm[];
    const uint32_t sbase = smem_u32(fsm);

    const int bh = blockIdx.y;                // 0..63
    const int b  = bh >> 4;
    const int h  = bh & 15;
    const int q0 = blockIdx.x * 128;

    const uint32_t* Qb = g_q + (size_t)bh * T_ * HD_;
    const uint32_t* Kb = g_k + (size_t)bh * T_ * HD_;
    const uint32_t* Vb = g_v + (size_t)bh * T_ * HD_;

    const int tid  = threadIdx.x;
    const int lane = tid & 31;
    const int wid  = tid >> 5;
    const int g = lane >> 2;       // quad row
    const int t = lane & 3;        // quad col
    const int qr = wid * 16;       // warp's q-row base within tile

    // shuffle-transpose source lanes (constant per thread)
    const int src0 = (lane & ~3) | (t >> 1);
    const int src1 = src0 + 2;
    const bool todd = (t & 1);

    // ---- Q fragments in registers: permuted layout -> LDG.64 pairs ----
    uint32_t qf[8][4];
    {
        const uint32_t* qrow0 = Qb + (size_t)(q0 + qr + g) * HD_;
        const uint32_t* qrow1 = qrow0 + 8 * HD_;
#pragma unroll
        for (int c8 = 0; c8 < 8; ++c8) {
            uint2 a02 = *(const uint2*)(qrow0 + c8 * 8 + 2 * t);
            uint2 a13 = *(const uint2*)(qrow1 + c8 * 8 + 2 * t);
            qf[c8][0] = a02.x;   // k = c8*8+t   (permuted slot 2t)
            qf[c8][2] = a02.y;   // k = c8*8+t+4 (permuted slot 2t+1)
            qf[c8][1] = a13.x;
            qf[c8][3] = a13.y;
        }
    }

    // cp.async tile loader: K tile (stride 68, permuted cols verbatim) + V (72)
    auto cp_kv = [&](int k0, int s) {
        const uint32_t koff = (uint32_t)s * FA_STG;
        const uint32_t voff = koff + FA_KSZ;
#pragma unroll
        for (int p = 0; p < 4; ++p) {
            int idx = tid * 4 + p;
            int row = idx >> 4;          // 0..63
            int c4  = (idx & 15) * 4;    // word offset 0..60
            cp16(sbase + (koff + (uint32_t)row * FA_KSTR + c4) * 4,
                 Kb + (size_t)(k0 + row) * HD_ + c4);
            cp16(sbase + (voff + (uint32_t)row * FA_VSTR + c4) * 4,
                 Vb + (size_t)(k0 + row) * HD_ + c4);
        }
    };

    // online softmax state (rows qr+g, qr+g+8) in log2 domain; per-lane l.
    float m0 = -3.0e38f, m1 = -3.0e38f, l0 = 0.0f, l1 = 0.0f;
    float oacc[8][4];
#pragma unroll
    for (int nt = 0; nt < 8; ++nt)
#pragma unroll
        for (int q = 0; q < 4; ++q) oacc[nt][q] = 0.0f;

    const int NT = T_ / 64;
    cp_kv(0, 0); CP_COMMIT();

    for (int kt = 0; kt < NT; ++kt) {
        CP_WAIT0();
        __syncthreads();
        if (kt + 1 < NT) {
            cp_kv((kt + 1) * 64, (kt + 1) & 1);
            CP_COMMIT();
        }

        const int cs = kt & 1;
        const uint32_t* Ks = fsm + cs * FA_STG;
        const uint32_t* Vs = fsm + cs * FA_STG + FA_KSZ;

        // ---- S = Q K^T (log2 domain): K frag pairs via LDS.64 ----
        float sacc[8][4];
#pragma unroll
        for (int nt = 0; nt < 8; ++nt)
#pragma unroll
            for (int q = 0; q < 4; ++q) sacc[nt][q] = 0.0f;

#pragma unroll
        for (int c8 = 0; c8 < 8; ++c8) {
#pragma unroll
            for (int nt = 0; nt < 8; ++nt) {
                uint2 kk2 = *(const uint2*)(Ks + (nt * 8 + g) * FA_KSTR + c8 * 8 + 2 * t);
                uint32_t bb[2] = {kk2.x, kk2.y};
                mma16n8k8(sacc[nt], qf[c8], bb);
            }
        }

        // ---- online softmax (exp2 domain; only MAX needs quad reduce) ----
        float tm0 = -3.0e38f, tm1 = -3.0e38f;
#pragma unroll
        for (int nt = 0; nt < 8; ++nt) {
            tm0 = fmaxf(tm0, fmaxf(sacc[nt][0], sacc[nt][1]));
            tm1 = fmaxf(tm1, fmaxf(sacc[nt][2], sacc[nt][3]));
        }
#pragma unroll
        for (int off = 1; off < 4; off <<= 1) {
            tm0 = fmaxf(tm0, __shfl_xor_sync(0xffffffffu, tm0, off));
            tm1 = fmaxf(tm1, __shfl_xor_sync(0xffffffffu, tm1, off));
        }
        const float mn0 = fmaxf(m0, tm0);
        const float mn1 = fmaxf(m1, tm1);
        const float corr0 = ex2f(m0 - mn0);
        const float corr1 = ex2f(m1 - mn1);
        m0 = mn0; m1 = mn1;

        float rs0 = 0.0f, rs1 = 0.0f;
#pragma unroll
        for (int nt = 0; nt < 8; ++nt) {
            float p0 = ex2f(sacc[nt][0] - mn0);
            float p1 = ex2f(sacc[nt][1] - mn0);
            float p2 = ex2f(sacc[nt][2] - mn1);
            float p3 = ex2f(sacc[nt][3] - mn1);
            sacc[nt][0] = p0; sacc[nt][1] = p1; sacc[nt][2] = p2; sacc[nt][3] = p3;
            rs0 += p0 + p1;
            rs1 += p2 + p3;
#pragma unroll
            for (int q = 0; q < 2; ++q) { oacc[nt][q] *= corr0; oacc[nt][q + 2] *= corr1; }
        }
        l0 = l0 * corr0 + rs0;     // per-lane partial (no shfl)
        l1 = l1 * corr1 + rs1;

        // ---- O += P V : P A-frags built by shfl transpose of C-frags ----
#pragma unroll
        for (int kk = 0; kk < 8; ++kk) {
            float x0 = __shfl_sync(0xffffffffu, sacc[kk][0], src0);
            float x1 = __shfl_sync(0xffffffffu, sacc[kk][1], src0);
            float x2 = __shfl_sync(0xffffffffu, sacc[kk][2], src0);
            float x3 = __shfl_sync(0xffffffffu, sacc[kk][3], src0);
            float y0 = __shfl_sync(0xffffffffu, sacc[kk][0], src1);
            float y1 = __shfl_sync(0xffffffffu, sacc[kk][1], src1);
            float y2 = __shfl_sync(0xffffffffu, sacc[kk][2], src1);
            float y3 = __shfl_sync(0xffffffffu, sacc[kk][3], src1);
            uint32_t a[4];
            a[0] = f2tf32(todd ? x1 : x0);
            a[1] = f2tf32(todd ? x3 : x2);
            a[2] = f2tf32(todd ? y1 : y0);
            a[3] = f2tf32(todd ? y3 : y2);
#pragma unroll
            for (int nt = 0; nt < 8; ++nt) {
                uint32_t bb[2];
                bb[0] = Vs[(kk * 8 + t) * FA_VSTR + nt * 8 + g];
                bb[1] = Vs[(kk * 8 + t + 4) * FA_VSTR + nt * 8 + g];
                mma16n8k8(oacc[nt], a, bb);
            }
        }
    }

    // ---- epilogue: reduce l across quad, normalize, write tf32 bits ----
#pragma unroll
    for (int off = 1; off < 4; off <<= 1) {
        l0 += __shfl_xor_sync(0xffffffffu, l0, off);
        l1 += __shfl_xor_sync(0xffffffffu, l1, off);
    }
    const float rl0 = 1.0f / l0;
    const float rl1 = 1.0f / l1;
    const size_t row0 = (size_t)(b * T_ + q0 + qr + g);
    const size_t row1 = row0 + 8;
#pragma unroll
    for (int nt = 0; nt < 8; ++nt) {
        const int col = h * HD_ + nt * 8 + 2 * t;
        *(uint2*)(g_y + row0 * C_ + col) =
            make_uint2(f2tf32(oacc[nt][0] * rl0), f2tf32(oacc[nt][1] * rl0));
        *(uint2*)(g_y + row1 * C_ + col) =
            make_uint2(f2tf32(oacc[nt][2] * rl1), f2tf32(oacc[nt][3] * rl1));
    }
}

// ============================================================================
// launch
// ============================================================================
extern "C" void kernel_launch(void* const* d_in, const int* in_sizes, int n_in,
                              void* d_out, int out_size)
{
    const float* x      = (const float*)d_in[0];
    const float* w_attn = (const float*)d_in[1];
    const float* w_proj = (const float*)d_in[2];
    float* out = (float*)d_out;

    float* qkv_ptr;  cudaGetSymbolAddress((void**)&qkv_ptr, g_qkv);
    uint32_t* y_ptr; cudaGetSymbolAddress((void**)&y_ptr,   g_y);
    uint32_t* xt;    cudaGetSymbolAddress((void**)&xt,  g_xt);
    uint32_t* wat;   cudaGetSymbolAddress((void**)&wat, g_wat);
    uint32_t* wpt;   cudaGetSymbolAddress((void**)&wpt, g_wpt);

    cudaFuncSetAttribute(flash_tc, cudaFuncAttributeMaxDynamicSharedMemorySize, FLASH_SMEM);
    cudaFuncSetAttribute(gemm_tc, cudaFuncAttributeMaxDynamicSharedMemorySize, GEMM_SMEM);

    // 0) convert inputs to tf32 bits; build rope table
    {
        int nx = M_ROWS * C_;
        to_tf32<<<(nx / 4 + 255) / 256, 256>>>(x, xt, nx);
        int na = QKV_N * C_;
        to_tf32<<<(na / 4 + 255) / 256, 256>>>(w_attn, wat, na);
        int np = C_ * C_;
        to_tf32<<<(np / 4 + 255) / 256, 256>>>(w_proj, wpt, np);
        rope_tab<<<(T_ * 32 + 255) / 256, 256>>>();
    }

    // 1) QKV = x @ w_attn^T : (8192, 3072)
    gemm_tc<<<dim3(QKV_N / 128, M_ROWS / 128), 256, GEMM_SMEM>>>(
        xt, wat, qkv_ptr, M_ROWS, QKV_N, C_);

    // 2) RoPE + rearrange (-> tf32 bits, k-permuted q/k)
    {
        int n = B_ * T_ * H_ * (HD_ / 2);
        rope_rearrange<<<(n + 255) / 256, 256>>>(qkv_ptr);
    }

    // 3) flash attention -> g_y (tf32 bits)
    flash_tc<<<dim3(T_ / 128, B_ * H_), 256, FLASH_SMEM>>>();

    // 4) out = y @ w_proj^T : (8192, 1024)
    gemm_tc<<<dim3(C_ / 128, M_ROWS / 128), 256, GEMM_SMEM>>>(
        y_ptr, wpt, out, M_ROWS, C_, C_);
}

// round 14
// speedup vs baseline: 1.3067x; 1.3067x over previous
#include <cuda_runtime.h>
#include <cuda_fp16.h>
#include <math.h>
#include <cstdint>

// Problem constants (fixed shapes from reference)
#define B_  4
#define T_  2048
#define C_  1024
#define H_  16
#define HD_ 64
#define M_ROWS (B_ * T_)          // 8192
#define QKV_N  (3 * C_)           // 3072

// -------- scratch (device globals; no allocation allowed) --------
__device__ float    g_qkv[(size_t)M_ROWS * QKV_N];     // fp32 (B*T, 3C)
__device__ uint32_t g_q[(size_t)B_ * H_ * T_ * HD_];   // tf32 bits, roped, *0.125*log2e
__device__ uint32_t g_k[(size_t)B_ * H_ * T_ * HD_];   // tf32 bits
__device__ uint32_t g_v[(size_t)B_ * H_ * T_ * HD_];   // tf32 bits
__device__ __half   g_yh[(size_t)M_ROWS * C_];         // f16 (B, T, C) attention out
__device__ __half   g_xh[(size_t)M_ROWS * C_];         // f16(x)
__device__ __half   g_wah[(size_t)QKV_N * C_];         // f16(w_attn)
__device__ __half   g_wph[(size_t)C_ * C_];            // f16(w_proj)
__device__ float2   g_rt[(size_t)T_ * 32];             // rope cos/sin table

// ---- helpers ----
__device__ __forceinline__ uint32_t f2tf32(float x) {
    uint32_t r; asm("cvt.rna.tf32.f32 %0, %1;" : "=r"(r) : "f"(x)); return r;
}
__device__ __forceinline__ float ex2f(float x) {
    float r; asm("ex2.approx.ftz.f32 %0, %1;" : "=f"(r) : "f"(x)); return r;
}
// tf32: D(16x8) += A(16x8) B(8x8)
__device__ __forceinline__ void mma16n8k8(float c[4], const uint32_t a[4], const uint32_t b[2]) {
    asm volatile(
        "mma.sync.aligned.m16n8k8.row.col.f32.tf32.tf32.f32 "
        "{%0,%1,%2,%3}, {%4,%5,%6,%7}, {%8,%9}, {%0,%1,%2,%3};"
        : "+f"(c[0]), "+f"(c[1]), "+f"(c[2]), "+f"(c[3])
        : "r"(a[0]), "r"(a[1]), "r"(a[2]), "r"(a[3]), "r"(b[0]), "r"(b[1]));
}
// f16: D(16x8) += A(16x16) B(16x8), fp32 accum
__device__ __forceinline__ void mma16n8k16h(float c[4], const uint32_t a[4], const uint32_t b[2]) {
    asm volatile(
        "mma.sync.aligned.m16n8k16.row.col.f32.f16.f16.f32 "
        "{%0,%1,%2,%3}, {%4,%5,%6,%7}, {%8,%9}, {%0,%1,%2,%3};"
        : "+f"(c[0]), "+f"(c[1]), "+f"(c[2]), "+f"(c[3])
        : "r"(a[0]), "r"(a[1]), "r"(a[2]), "r"(a[3]), "r"(b[0]), "r"(b[1]));
}
__device__ __forceinline__ uint32_t smem_u32(const void* p) {
    uint32_t a;
    asm("{ .reg .u64 t; cvta.to.shared.u64 t, %1; cvt.u32.u64 %0, t; }" : "=r"(a) : "l"(p));
    return a;
}
__device__ __forceinline__ void cp16(uint32_t dst, const void* src) {
    asm volatile("cp.async.cg.shared.global [%0], [%1], 16;" :: "r"(dst), "l"(src));
}
#define CP_COMMIT() asm volatile("cp.async.commit_group;" ::: "memory")
#define CP_WAIT1()  asm volatile("cp.async.wait_group 1;" ::: "memory")
#define CP_WAIT0()  asm volatile("cp.async.wait_group 0;" ::: "memory")

// ============================================================================
// input converter: fp32 -> f16 (n % 8 == 0)
// ============================================================================
__global__ __launch_bounds__(256) void to_f16(const float* __restrict__ in,
                                              __half* __restrict__ out, int n)
{
    int i = (blockIdx.x * blockDim.x + threadIdx.x) * 8;
    if (i < n) {
        float4 v0 = *(const float4*)(in + i);
        float4 v1 = *(const float4*)(in + i + 4);
        __half2 h0 = __floats2half2_rn(v0.x, v0.y);
        __half2 h1 = __floats2half2_rn(v0.z, v0.w);
        __half2 h2 = __floats2half2_rn(v1.x, v1.y);
        __half2 h3 = __floats2half2_rn(v1.z, v1.w);
        uint4 o;
        o.x = *(uint32_t*)&h0; o.y = *(uint32_t*)&h1;
        o.z = *(uint32_t*)&h2; o.w = *(uint32_t*)&h3;
        *(uint4*)(out + i) = o;
    }
}

// ============================================================================
// FP16 tensor-core GEMM (NT): C[m,n] = sum_k A[m*K+k]*B[n*K+k], fp32 accum.
// CTA 128x128, BK=64 (rows of 64 halves = 32 words: IDENTICAL smem layout,
// swizzle and fragment addressing as the verified tf32/BK=32 kernel).
// 3-stage cp.async ring, single sync per tile, 2 CTAs/SM.
// ============================================================================
#define GEMM_SMEM (24576 * 4)    // 3 stages x (A 4096 + B 4096) words = 96KB

__global__ void __launch_bounds__(256, 2) gemm_f16(
    const __half* __restrict__ A, const __half* __restrict__ Bm,
    float* __restrict__ C, int M, int N, int K)
{
    extern __shared__ uint32_t sm[];
    const uint32_t sbase = smem_u32(sm);

    const int tid  = threadIdx.x;
    const int lane = tid & 31;
    const int wid  = tid >> 5;
    const int wm = wid & 1;
    const int wn = wid >> 1;
    const int g = lane >> 2;
    const int t = lane & 3;
    const int bm = blockIdx.y * 128;
    const int bn = blockIdx.x * 128;

    const int lrow = tid >> 3;       // 0..31 (+p*32)
    const int lu   = tid & 7;        // 16B unit (8 halves)

    float acc[4][4][4];
#pragma unroll
    for (int mt = 0; mt < 4; ++mt)
#pragma unroll
        for (int nt = 0; nt < 4; ++nt)
#pragma unroll
            for (int q = 0; q < 4; ++q) acc[mt][nt][q] = 0.0f;

    auto cp_tile = [&](int k0, int s) {
#pragma unroll
        for (int p = 0; p < 4; ++p) {
            int row = lrow + p * 32;
            int u = lu ^ (row & 7);
            cp16(sbase + (uint32_t)(s * 4096 + row * 32 + u * 4) * 4,
                 A + (size_t)(bm + row) * K + k0 + lu * 8);
            cp16(sbase + (uint32_t)(12288 + s * 4096 + row * 32 + u * 4) * 4,
                 Bm + (size_t)(bn + row) * K + k0 + lu * 8);
        }
    };

    const int nk = K >> 6;           // BK = 64 halves
    cp_tile(0, 0); CP_COMMIT();
    cp_tile(64, 1); CP_COMMIT();

    for (int kt = 0; kt < nk; ++kt) {
        if (kt + 1 < nk) CP_WAIT1(); else CP_WAIT0();
        __syncthreads();

        const int cs = kt % 3;
        const uint32_t* Asb = sm + cs * 4096;
        const uint32_t* Bsb = sm + 12288 + cs * 4096;

#pragma unroll
        for (int s = 0; s < 4; ++s) {            // 4 k16-steps per BK=64
            const int u0 = (2 * s) ^ g;
            const int u1 = u0 ^ 1;

            uint32_t af[4][4];
#pragma unroll
            for (int mt = 0; mt < 4; ++mt) {
                const int r0 = wm * 64 + mt * 16 + g;
                af[mt][0] = Asb[r0 * 32 + u0 * 4 + t];        // row g,   k 16s+2t..+1
                af[mt][1] = Asb[(r0 + 8) * 32 + u0 * 4 + t];  // row g+8, k-lo
                af[mt][2] = Asb[r0 * 32 + u1 * 4 + t];        // row g,   k 16s+8+2t..+1
                af[mt][3] = Asb[(r0 + 8) * 32 + u1 * 4 + t];  // row g+8, k-hi
            }
            uint32_t bf[4][2];
#pragma unroll
            for (int nt = 0; nt < 4; ++nt) {
                const int n0 = wn * 32 + nt * 8 + g;
                bf[nt][0] = Bsb[n0 * 32 + u0 * 4 + t];
                bf[nt][1] = Bsb[n0 * 32 + u1 * 4 + t];
            }
#pragma unroll
            for (int mt = 0; mt < 4; ++mt)
#pragma unroll
                for (int nt = 0; nt < 4; ++nt)
                    mma16n8k16h(acc[mt][nt], af[mt], bf[nt]);
        }

        if (kt + 2 < nk) {
            cp_tile((kt + 2) << 6, (kt + 2) % 3);
            CP_COMMIT();
        }
    }

#pragma unroll
    for (int mt = 0; mt < 4; ++mt) {
        const int row = bm + wm * 64 + mt * 16 + g;
#pragma unroll
        for (int nt = 0; nt < 4; ++nt) {
            const int col = bn + wn * 32 + nt * 8 + 2 * t;
            *(float2*)(C + (size_t)row * N + col)       = make_float2(acc[mt][nt][0], acc[mt][nt][1]);
            *(float2*)(C + (size_t)(row + 8) * N + col) = make_float2(acc[mt][nt][2], acc[mt][nt][3]);
        }
    }
}

// ============================================================================
// RoPE table: cos/sin for (t, i) computed once per launch (fp64 accurate)
// ============================================================================
__global__ __launch_bounds__(256) void rope_tab()
{
    int idx = blockIdx.x * blockDim.x + threadIdx.x;
    if (idx >= T_ * 32) return;
    int i = idx & 31;
    int t = idx >> 5;
    double inv = exp2(-(double)i * (13.287712379549449595 / 32.0)); // 10000^(-i/32)
    double ds, dc;
    sincos((double)t * inv, &ds, &dc);
    g_rt[idx] = make_float2((float)dc, (float)ds);
}

// ============================================================================
// RoPE + rearrange: qkv (fp32) -> Q/K/V tf32 bits. Q scaled by 0.125*log2(e).
// (exact Round-11 version: natural layout, no permutation)
// ============================================================================
__global__ __launch_bounds__(256) void rope_rearrange(const float* __restrict__ qkv)
{
    int idx = blockIdx.x * blockDim.x + threadIdx.x;
    if (idx >= B_ * T_ * H_ * (HD_ / 2)) return;

    int i = idx & 31;               // pair index 0..31
    int h = (idx >> 5) & 15;
    int t = (idx >> 9) & 2047;
    int b = idx >> 20;

    const float* src = qkv + (size_t)(b * T_ + t) * QKV_N + h * HD_ + 2 * i;

    float2 cs = g_rt[t * 32 + i];
    float c = cs.x, s = cs.y;

    float q0 = src[0],       q1 = src[1];
    float k0 = src[C_],      k1 = src[C_ + 1];
    float2 v2 = *(const float2*)(src + 2 * C_);

    size_t dst = ((size_t)(b * H_ + h) * T_ + t) * HD_ + 2 * i;
    const float qs = 0.125f * 1.44269504088896340736f;  // 1/sqrt(64) * log2(e)
    g_q[dst]     = f2tf32((q0 * c - q1 * s) * qs);
    g_q[dst + 1] = f2tf32((q0 * s + q1 * c) * qs);
    g_k[dst]     = f2tf32(k0 * c - k1 * s);
    g_k[dst + 1] = f2tf32(k0 * s + k1 * c);
    g_v[dst]     = f2tf32(v2.x);
    g_v[dst + 1] = f2tf32(v2.y);
}

// ============================================================================
// Tensor-core flash attention (exact Round-11 v6, except epilogue emits f16):
// Bq=128, Bk=64, hd=64. 256 threads (8 warps), warp = 16 q-rows. Q frags in
// registers. K/V 2-stage cp.async ring, single sync per tile, prefetch after
// sync. P transpose via shfl. exp2 softmax, deferred l-sum. smem 70KB.
// ============================================================================
#define FA_KSTR 68
#define FA_VSTR 72
#define FA_KSZ  (64 * FA_KSTR)                    // 4352 words
#define FA_VSZ  (64 * FA_VSTR)                    // 4608 words
#define FA_STG  (FA_KSZ + FA_VSZ)                 // 8960 words per stage
#define FLASH_SMEM (2 * FA_STG * 4)               // 71680 bytes

__global__ void __launch_bounds__(256, 2) flash_tc()
{
    extern __shared__ uint32_t fsm[];
    const uint32_t sbase = smem_u32(fsm);

    const int bh = blockIdx.y;                // 0..63
    const int b  = bh >> 4;
    const int h  = bh & 15;
    const int q0 = blockIdx.x * 128;

    const uint32_t* Qb = g_q + (size_t)bh * T_ * HD_;
    const uint32_t* Kb = g_k + (size_t)bh * T_ * HD_;
    const uint32_t* Vb = g_v + (size_t)bh * T_ * HD_;

    const int tid  = threadIdx.x;
    const int lane = tid & 31;
    const int wid  = tid >> 5;
    const int g = lane >> 2;       // quad row
    const int t = lane & 3;        // quad col
    const int qr = wid * 16;       // warp's q-row base within tile

    // shuffle-transpose source lanes (constant per thread)
    const int src0 = (lane & ~3) | (t >> 1);
    const int src1 = src0 + 2;
    const bool todd = (t & 1);

    // ---- Q fragments in registers (loop-invariant, tf32, log2e-scaled) ----
    uint32_t qf[8][4];
    {
        const uint32_t* qrow0 = Qb + (size_t)(q0 + qr + g) * HD_;
        const uint32_t* qrow1 = qrow0 + 8 * HD_;
#pragma unroll
        for (int c8 = 0; c8 < 8; ++c8) {
            qf[c8][0] = qrow0[c8 * 8 + t];
            qf[c8][1] = qrow1[c8 * 8 + t];
            qf[c8][2] = qrow0[c8 * 8 + t + 4];
            qf[c8][3] = qrow1[c8 * 8 + t + 4];
        }
    }

    // cp.async tile loader: K tile (stride 68) + V tile (stride 72)
    auto cp_kv = [&](int k0, int s) {
        const uint32_t koff = (uint32_t)s * FA_STG;
        const uint32_t voff = koff + FA_KSZ;
#pragma unroll
        for (int p = 0; p < 4; ++p) {
            int idx = tid * 4 + p;
            int row = idx >> 4;          // 0..63
            int c4  = (idx & 15) * 4;    // word offset 0..60
            cp16(sbase + (koff + (uint32_t)row * FA_KSTR + c4) * 4,
                 Kb + (size_t)(k0 + row) * HD_ + c4);
            cp16(sbase + (voff + (uint32_t)row * FA_VSTR + c4) * 4,
                 Vb + (size_t)(k0 + row) * HD_ + c4);
        }
    };

    // online softmax state (rows qr+g, qr+g+8) in log2 domain; per-lane l.
    float m0 = -3.0e38f, m1 = -3.0e38f, l0 = 0.0f, l1 = 0.0f;
    float oacc[8][4];
#pragma unroll
    for (int nt = 0; nt < 8; ++nt)
#pragma unroll
        for (int q = 0; q < 4; ++q) oacc[nt][q] = 0.0f;

    const int NT = T_ / 64;
    cp_kv(0, 0); CP_COMMIT();

    for (int kt = 0; kt < NT; ++kt) {
        CP_WAIT0();
        __syncthreads();
        if (kt + 1 < NT) {
            cp_kv((kt + 1) * 64, (kt + 1) & 1);
            CP_COMMIT();
        }

        const int cs = kt & 1;
        const uint32_t* Ks = fsm + cs * FA_STG;
        const uint32_t* Vs = fsm + cs * FA_STG + FA_KSZ;

        // ---- S = Q K^T (log2 domain): warp computes 16x64 ----
        float sacc[8][4];
#pragma unroll
        for (int nt = 0; nt < 8; ++nt)
#pragma unroll
            for (int q = 0; q < 4; ++q) sacc[nt][q] = 0.0f;

#pragma unroll
        for (int c8 = 0; c8 < 8; ++c8) {
#pragma unroll
            for (int nt = 0; nt < 8; ++nt) {
                uint32_t bb[2];
                bb[0] = Ks[(nt * 8 + g) * FA_KSTR + c8 * 8 + t];
                bb[1] = Ks[(nt * 8 + g) * FA_KSTR + c8 * 8 + t + 4];
                mma16n8k8(sacc[nt], qf[c8], bb);
            }
        }

        // ---- online softmax (exp2 domain; only MAX needs quad reduce) ----
        float tm0 = -3.0e38f, tm1 = -3.0e38f;
#pragma unroll
        for (int nt = 0; nt < 8; ++nt) {
            tm0 = fmaxf(tm0, fmaxf(sacc[nt][0], sacc[nt][1]));
            tm1 = fmaxf(tm1, fmaxf(sacc[nt][2], sacc[nt][3]));
        }
#pragma unroll
        for (int off = 1; off < 4; off <<= 1) {
            tm0 = fmaxf(tm0, __shfl_xor_sync(0xffffffffu, tm0, off));
            tm1 = fmaxf(tm1, __shfl_xor_sync(0xffffffffu, tm1, off));
        }
        const float mn0 = fmaxf(m0, tm0);
        const float mn1 = fmaxf(m1, tm1);
        const float corr0 = ex2f(m0 - mn0);
        const float corr1 = ex2f(m1 - mn1);
        m0 = mn0; m1 = mn1;

        float rs0 = 0.0f, rs1 = 0.0f;
#pragma unroll
        for (int nt = 0; nt < 8; ++nt) {
            float p0 = ex2f(sacc[nt][0] - mn0);
            float p1 = ex2f(sacc[nt][1] - mn0);
            float p2 = ex2f(sacc[nt][2] - mn1);
            float p3 = ex2f(sacc[nt][3] - mn1);
            sacc[nt][0] = p0; sacc[nt][1] = p1; sacc[nt][2] = p2; sacc[nt][3] = p3;
            rs0 += p0 + p1;
            rs1 += p2 + p3;
#pragma unroll
            for (int q = 0; q < 2; ++q) { oacc[nt][q] *= corr0; oacc[nt][q + 2] *= corr1; }
        }
        l0 = l0 * corr0 + rs0;     // per-lane partial (no shfl)
        l1 = l1 * corr1 + rs1;

        // ---- O += P V : P A-frags built by shfl transpose of C-frags ----
#pragma unroll
        for (int kk = 0; kk < 8; ++kk) {
            float x0 = __shfl_sync(0xffffffffu, sacc[kk][0], src0);
            float x1 = __shfl_sync(0xffffffffu, sacc[kk][1], src0);
            float x2 = __shfl_sync(0xffffffffu, sacc[kk][2], src0);
            float x3 = __shfl_sync(0xffffffffu, sacc[kk][3], src0);
            float y0 = __shfl_sync(0xffffffffu, sacc[kk][0], src1);
            float y1 = __shfl_sync(0xffffffffu, sacc[kk][1], src1);
            float y2 = __shfl_sync(0xffffffffu, sacc[kk][2], src1);
            float y3 = __shfl_sync(0xffffffffu, sacc[kk][3], src1);
            uint32_t a[4];
            a[0] = f2tf32(todd ? x1 : x0);
            a[1] = f2tf32(todd ? x3 : x2);
            a[2] = f2tf32(todd ? y1 : y0);
            a[3] = f2tf32(todd ? y3 : y2);
#pragma unroll
            for (int nt = 0; nt < 8; ++nt) {
                uint32_t bb[2];
                bb[0] = Vs[(kk * 8 + t) * FA_VSTR + nt * 8 + g];
                bb[1] = Vs[(kk * 8 + t + 4) * FA_VSTR + nt * 8 + g];
                mma16n8k8(oacc[nt], a, bb);
            }
        }
    }

    // ---- epilogue: reduce l across quad, normalize, write f16 (for proj) ----
#pragma unroll
    for (int off = 1; off < 4; off <<= 1) {
        l0 += __shfl_xor_sync(0xffffffffu, l0, off);
        l1 += __shfl_xor_sync(0xffffffffu, l1, off);
    }
    const float rl0 = 1.0f / l0;
    const float rl1 = 1.0f / l1;
    const size_t row0 = (size_t)(b * T_ + q0 + qr + g);
    const size_t row1 = row0 + 8;
#pragma unroll
    for (int nt = 0; nt < 8; ++nt) {
        const int col = h * HD_ + nt * 8 + 2 * t;
        *(__half2*)(g_yh + row0 * C_ + col) =
            __floats2half2_rn(oacc[nt][0] * rl0, oacc[nt][1] * rl0);
        *(__half2*)(g_yh + row1 * C_ + col) =
            __floats2half2_rn(oacc[nt][2] * rl1, oacc[nt][3] * rl1);
    }
}

// ============================================================================
// launch
// ============================================================================
extern "C" void kernel_launch(void* const* d_in, const int* in_sizes, int n_in,
                              void* d_out, int out_size)
{
    const float* x      = (const float*)d_in[0];
    const float* w_attn = (const float*)d_in[1];
    const float* w_proj = (const float*)d_in[2];
    float* out = (float*)d_out;

    float* qkv_ptr; cudaGetSymbolAddress((void**)&qkv_ptr, g_qkv);
    __half* yh;     cudaGetSymbolAddress((void**)&yh,  g_yh);
    __half* xh;     cudaGetSymbolAddress((void**)&xh,  g_xh);
    __half* wah;    cudaGetSymbolAddress((void**)&wah, g_wah);
    __half* wph;    cudaGetSymbolAddress((void**)&wph, g_wph);

    cudaFuncSetAttribute(flash_tc, cudaFuncAttributeMaxDynamicSharedMemorySize, FLASH_SMEM);
    cudaFuncSetAttribute(gemm_f16, cudaFuncAttributeMaxDynamicSharedMemorySize, GEMM_SMEM);

    // 0) convert inputs to f16; build rope table
    {
        int nx = M_ROWS * C_;
        to_f16<<<(nx / 8 + 255) / 256, 256>>>(x, xh, nx);
        int na = QKV_N * C_;
        to_f16<<<(na / 8 + 255) / 256, 256>>>(w_attn, wah, na);
        int np = C_ * C_;
        to_f16<<<(np / 8 + 255) / 256, 256>>>(w_proj, wph, np);
        rope_tab<<<(T_ * 32 + 255) / 256, 256>>>();
    }

    // 1) QKV = x @ w_attn^T : (8192, 3072), f16 tensor cores
    gemm_f16<<<dim3(QKV_N / 128, M_ROWS / 128), 256, GEMM_SMEM>>>(
        xh, wah, qkv_ptr, M_ROWS, QKV_N, C_);

    // 2) RoPE + rearrange (-> tf32 bits; Q scaled by 0.125*log2e)
    {
        int n = B_ * T_ * H_ * (HD_ / 2);
        rope_rearrange<<<(n + 255) / 256, 256>>>(qkv_ptr);
    }

    // 3) flash attention (tf32) -> g_yh (f16)
    flash_tc<<<dim3(T_ / 128, B_ * H_), 256, FLASH_SMEM>>>();

    // 4) out = y @ w_proj^T : (8192, 1024), f16 tensor cores
    gemm_f16<<<dim3(C_ / 128, M_ROWS / 128), 256, GEMM_SMEM>>>(
        yh, wph, out, M_ROWS, C_, C_);
}

// round 15
// speedup vs baseline: 1.9862x; 1.5200x over previous
#include <cuda_runtime.h>
#include <cuda_fp16.h>
#include <math.h>
#include <cstdint>

// Problem constants (fixed shapes from reference)
#define B_  4
#define T_  2048
#define C_  1024
#define H_  16
#define HD_ 64
#define M_ROWS (B_ * T_)          // 8192
#define QKV_N  (3 * C_)           // 3072

// -------- scratch (device globals; no allocation allowed) --------
__device__ float    g_qkv[(size_t)M_ROWS * QKV_N];     // fp32 (B*T, 3C)
__device__ __half   g_qh[(size_t)B_ * H_ * T_ * HD_];  // f16, roped, *0.125*log2e
__device__ __half   g_kh[(size_t)B_ * H_ * T_ * HD_];  // f16, roped
__device__ __half   g_vt[(size_t)B_ * H_ * HD_ * T_];  // f16, V TRANSPOSED (bh, d, t)
__device__ __half   g_yh[(size_t)M_ROWS * C_];         // f16 (B, T, C) attention out
__device__ __half   g_xh[(size_t)M_ROWS * C_];         // f16(x)
__device__ __half   g_wah[(size_t)QKV_N * C_];         // f16(w_attn)
__device__ __half   g_wph[(size_t)C_ * C_];            // f16(w_proj)
__device__ float2   g_rt[(size_t)T_ * 32];             // rope cos/sin table

// ---- helpers ----
__device__ __forceinline__ float ex2f(float x) {
    float r; asm("ex2.approx.ftz.f32 %0, %1;" : "=f"(r) : "f"(x)); return r;
}
// f16: D(16x8) += A(16x16) B(16x8), fp32 accum
__device__ __forceinline__ void mma16n8k16h(float c[4], const uint32_t a[4], const uint32_t b[2]) {
    asm volatile(
        "mma.sync.aligned.m16n8k16.row.col.f32.f16.f16.f32 "
        "{%0,%1,%2,%3}, {%4,%5,%6,%7}, {%8,%9}, {%0,%1,%2,%3};"
        : "+f"(c[0]), "+f"(c[1]), "+f"(c[2]), "+f"(c[3])
        : "r"(a[0]), "r"(a[1]), "r"(a[2]), "r"(a[3]), "r"(b[0]), "r"(b[1]));
}
__device__ __forceinline__ uint32_t smem_u32(const void* p) {
    uint32_t a;
    asm("{ .reg .u64 t; cvta.to.shared.u64 t, %1; cvt.u32.u64 %0, t; }" : "=r"(a) : "l"(p));
    return a;
}
__device__ __forceinline__ void cp16(uint32_t dst, const void* src) {
    asm volatile("cp.async.cg.shared.global [%0], [%1], 16;" :: "r"(dst), "l"(src));
}
__device__ __forceinline__ uint32_t packh2(float lo, float hi) {
    __half2 h = __floats2half2_rn(lo, hi);
    return *(uint32_t*)&h;
}
#define CP_COMMIT() asm volatile("cp.async.commit_group;" ::: "memory")
#define CP_WAIT1()  asm volatile("cp.async.wait_group 1;" ::: "memory")
#define CP_WAIT0()  asm volatile("cp.async.wait_group 0;" ::: "memory")

// ============================================================================
// input converter: fp32 -> f16 (n % 8 == 0)
// ============================================================================
__global__ __launch_bounds__(256) void to_f16(const float* __restrict__ in,
                                              __half* __restrict__ out, int n)
{
    int i = (blockIdx.x * blockDim.x + threadIdx.x) * 8;
    if (i < n) {
        float4 v0 = *(const float4*)(in + i);
        float4 v1 = *(const float4*)(in + i + 4);
        uint4 o;
        o.x = packh2(v0.x, v0.y); o.y = packh2(v0.z, v0.w);
        o.z = packh2(v1.x, v1.y); o.w = packh2(v1.z, v1.w);
        *(uint4*)(out + i) = o;
    }
}

// ============================================================================
// FP16 tensor-core GEMM (NT) — unchanged from Round 14 passing version.
// ============================================================================
#define GEMM_SMEM (24576 * 4)    // 3 stages x (A 4096 + B 4096) words = 96KB

__global__ void __launch_bounds__(256, 2) gemm_f16(
    const __half* __restrict__ A, const __half* __restrict__ Bm,
    float* __restrict__ C, int M, int N, int K)
{
    extern __shared__ uint32_t sm[];
    const uint32_t sbase = smem_u32(sm);

    const int tid  = threadIdx.x;
    const int lane = tid & 31;
    const int wid  = tid >> 5;
    const int wm = wid & 1;
    const int wn = wid >> 1;
    const int g = lane >> 2;
    const int t = lane & 3;
    const int bm = blockIdx.y * 128;
    const int bn = blockIdx.x * 128;

    const int lrow = tid >> 3;       // 0..31 (+p*32)
    const int lu   = tid & 7;        // 16B unit (8 halves)

    float acc[4][4][4];
#pragma unroll
    for (int mt = 0; mt < 4; ++mt)
#pragma unroll
        for (int nt = 0; nt < 4; ++nt)
#pragma unroll
            for (int q = 0; q < 4; ++q) acc[mt][nt][q] = 0.0f;

    auto cp_tile = [&](int k0, int s) {
#pragma unroll
        for (int p = 0; p < 4; ++p) {
            int row = lrow + p * 32;
            int u = lu ^ (row & 7);
            cp16(sbase + (uint32_t)(s * 4096 + row * 32 + u * 4) * 4,
                 A + (size_t)(bm + row) * K + k0 + lu * 8);
            cp16(sbase + (uint32_t)(12288 + s * 4096 + row * 32 + u * 4) * 4,
                 Bm + (size_t)(bn + row) * K + k0 + lu * 8);
        }
    };

    const int nk = K >> 6;           // BK = 64 halves
    cp_tile(0, 0); CP_COMMIT();
    cp_tile(64, 1); CP_COMMIT();

    for (int kt = 0; kt < nk; ++kt) {
        if (kt + 1 < nk) CP_WAIT1(); else CP_WAIT0();
        __syncthreads();

        const int cs = kt % 3;
        const uint32_t* Asb = sm + cs * 4096;
        const uint32_t* Bsb = sm + 12288 + cs * 4096;

#pragma unroll
        for (int s = 0; s < 4; ++s) {            // 4 k16-steps per BK=64
            const int u0 = (2 * s) ^ g;
            const int u1 = u0 ^ 1;

            uint32_t af[4][4];
#pragma unroll
            for (int mt = 0; mt < 4; ++mt) {
                const int r0 = wm * 64 + mt * 16 + g;
                af[mt][0] = Asb[r0 * 32 + u0 * 4 + t];
                af[mt][1] = Asb[(r0 + 8) * 32 + u0 * 4 + t];
                af[mt][2] = Asb[r0 * 32 + u1 * 4 + t];
                af[mt][3] = Asb[(r0 + 8) * 32 + u1 * 4 + t];
            }
            uint32_t bf[4][2];
#pragma unroll
            for (int nt = 0; nt < 4; ++nt) {
                const int n0 = wn * 32 + nt * 8 + g;
                bf[nt][0] = Bsb[n0 * 32 + u0 * 4 + t];
                bf[nt][1] = Bsb[n0 * 32 + u1 * 4 + t];
            }
#pragma unroll
            for (int mt = 0; mt < 4; ++mt)
#pragma unroll
                for (int nt = 0; nt < 4; ++nt)
                    mma16n8k16h(acc[mt][nt], af[mt], bf[nt]);
        }

        if (kt + 2 < nk) {
            cp_tile((kt + 2) << 6, (kt + 2) % 3);
            CP_COMMIT();
        }
    }

#pragma unroll
    for (int mt = 0; mt < 4; ++mt) {
        const int row = bm + wm * 64 + mt * 16 + g;
#pragma unroll
        for (int nt = 0; nt < 4; ++nt) {
            const int col = bn + wn * 32 + nt * 8 + 2 * t;
            *(float2*)(C + (size_t)row * N + col)       = make_float2(acc[mt][nt][0], acc[mt][nt][1]);
            *(float2*)(C + (size_t)(row + 8) * N + col) = make_float2(acc[mt][nt][2], acc[mt][nt][3]);
        }
    }
}

// ============================================================================
// RoPE table: cos/sin for (t, i) computed once per launch (fp64 accurate)
// ============================================================================
__global__ __launch_bounds__(256) void rope_tab()
{
    int idx = blockIdx.x * blockDim.x + threadIdx.x;
    if (idx >= T_ * 32) return;
    int i = idx & 31;
    int t = idx >> 5;
    double inv = exp2(-(double)i * (13.287712379549449595 / 32.0)); // 10000^(-i/32)
    double ds, dc;
    sincos((double)t * inv, &ds, &dc);
    g_rt[idx] = make_float2((float)dc, (float)ds);
}

// ============================================================================
// RoPE + rearrange: qkv (fp32) -> Q/K f16 (roped; Q *0.125*log2e), V f16
// TRANSPOSED to (bh, d, t) for the f16 PV B-operand.
// ============================================================================
__global__ __launch_bounds__(256) void rope_rearrange(const float* __restrict__ qkv)
{
    int idx = blockIdx.x * blockDim.x + threadIdx.x;
    if (idx >= B_ * T_ * H_ * (HD_ / 2)) return;

    int i = idx & 31;               // pair index 0..31
    int h = (idx >> 5) & 15;
    int t = (idx >> 9) & 2047;
    int b = idx >> 20;

    const float* src = qkv + (size_t)(b * T_ + t) * QKV_N + h * HD_ + 2 * i;

    float2 cs = g_rt[t * 32 + i];
    float c = cs.x, s = cs.y;

    float q0 = src[0],       q1 = src[1];
    float k0 = src[C_],      k1 = src[C_ + 1];
    float2 v2 = *(const float2*)(src + 2 * C_);

    const int bh = b * H_ + h;
    size_t dst = ((size_t)bh * T_ + t) * HD_ + 2 * i;
    const float qs = 0.125f * 1.44269504088896340736f;  // 1/sqrt(64) * log2(e)
    uint32_t qp = packh2((q0 * c - q1 * s) * qs, (q0 * s + q1 * c) * qs);
    uint32_t kp = packh2(k0 * c - k1 * s, k0 * s + k1 * c);
    *(uint32_t*)(g_qh + dst) = qp;
    *(uint32_t*)(g_kh + dst) = kp;

    // V transposed: g_vt[bh][d][t]
    size_t vbase = ((size_t)bh * HD_ + 2 * i) * T_ + t;
    g_vt[vbase]      = __float2half_rn(v2.x);
    g_vt[vbase + T_] = __float2half_rn(v2.y);
}

// ============================================================================
// FP16 tensor-core flash attention v8: Bq=128, Bk=64, hd=64. 256 threads
// (8 warps), warp = 16 q-rows. Q frags in registers (f16 pairs, 32-bit LDG).
// K key-major smem (stride 36 words), V d-major smem (stride 36 words), both
// via 2-stage cp.async ring, single sync/tile, prefetch after sync.
// P C-frags feed PV A-frags DIRECTLY (f16 layout match — no shfl transpose).
// exp2 softmax, deferred l-sum. smem 36KB -> 2 CTAs/SM.
// ============================================================================
#define FA_STR  36                                 // words per row (32 + 4 pad)
#define FA_TSZ  (64 * FA_STR)                      // 2304 words per tile
#define FA_STG  (2 * FA_TSZ)                       // K + V per stage
#define FLASH_SMEM (2 * FA_STG * 4)                // 36864 bytes

__global__ void __launch_bounds__(256, 2) flash_tc()
{
    extern __shared__ uint32_t fsm[];
    const uint32_t sbase = smem_u32(fsm);

    const int bh = blockIdx.y;                // 0..63
    const int b  = bh >> 4;
    const int h  = bh & 15;
    const int q0 = blockIdx.x * 128;

    const __half* Qb  = g_qh + (size_t)bh * T_ * HD_;
    const __half* Kb  = g_kh + (size_t)bh * T_ * HD_;
    const __half* Vtb = g_vt + (size_t)bh * HD_ * T_;

    const int tid  = threadIdx.x;
    const int lane = tid & 31;
    const int wid  = tid >> 5;
    const int g = lane >> 2;       // quad row
    const int t = lane & 3;        // quad col
    const int qr = wid * 16;       // warp's q-row base within tile

    // ---- Q fragments in registers (f16, loop-invariant) ----
    uint32_t qf[4][4];
    {
        const __half* qrow0 = Qb + (size_t)(q0 + qr + g) * HD_;
        const __half* qrow1 = qrow0 + 8 * HD_;
#pragma unroll
        for (int s = 0; s < 4; ++s) {
            qf[s][0] = *(const uint32_t*)(qrow0 + 16 * s + 2 * t);
            qf[s][1] = *(const uint32_t*)(qrow1 + 16 * s + 2 * t);
            qf[s][2] = *(const uint32_t*)(qrow0 + 16 * s + 8 + 2 * t);
            qf[s][3] = *(const uint32_t*)(qrow1 + 16 * s + 8 + 2 * t);
        }
    }

    // cp.async tile loader: K [key][d] rows of 64 halves; V [d][key] rows of
    // 64 halves. 512 16B-chunks each; 256 threads x 2 chunks per array.
    auto cp_kv = [&](int k0, int s) {
        const uint32_t koff = (uint32_t)s * FA_STG;
        const uint32_t voff = koff + FA_TSZ;
#pragma unroll
        for (int p = 0; p < 2; ++p) {
            int idx = tid * 2 + p;
            int row = idx >> 3;          // 0..63
            int ch  = idx & 7;           // 16B chunk (8 halves)
            cp16(sbase + (koff + (uint32_t)row * FA_STR + ch * 4) * 4,
                 Kb + (size_t)(k0 + row) * HD_ + ch * 8);
            cp16(sbase + (voff + (uint32_t)row * FA_STR + ch * 4) * 4,
                 Vtb + (size_t)row * T_ + k0 + ch * 8);
        }
    };

    // online softmax state (rows qr+g, qr+g+8) in log2 domain; per-lane l.
    float m0 = -3.0e38f, m1 = -3.0e38f, l0 = 0.0f, l1 = 0.0f;
    float oacc[8][4];
#pragma unroll
    for (int nt = 0; nt < 8; ++nt)
#pragma unroll
        for (int q = 0; q < 4; ++q) oacc[nt][q] = 0.0f;

    const int NT = T_ / 64;
    cp_kv(0, 0); CP_COMMIT();

    for (int kt = 0; kt < NT; ++kt) {
        CP_WAIT0();
        __syncthreads();
        if (kt + 1 < NT) {
            cp_kv((kt + 1) * 64, (kt + 1) & 1);
            CP_COMMIT();
        }

        const int cs = kt & 1;
        const uint32_t* Ks = fsm + cs * FA_STG;
        const uint32_t* Vs = fsm + cs * FA_STG + FA_TSZ;

        // ---- S = Q K^T (log2 domain): 4 k16-steps x 8 key-blocks ----
        float sacc[8][4];
#pragma unroll
        for (int nt = 0; nt < 8; ++nt)
#pragma unroll
            for (int q = 0; q < 4; ++q) sacc[nt][q] = 0.0f;

#pragma unroll
        for (int s = 0; s < 4; ++s) {
#pragma unroll
            for (int nt = 0; nt < 8; ++nt) {
                uint32_t bb[2];
                bb[0] = Ks[(nt * 8 + g) * FA_STR + s * 8 + t];
                bb[1] = Ks[(nt * 8 + g) * FA_STR + s * 8 + 4 + t];
                mma16n8k16h(sacc[nt], qf[s], bb);
            }
        }

        // ---- online softmax (exp2 domain; only MAX needs quad reduce) ----
        float tm0 = -3.0e38f, tm1 = -3.0e38f;
#pragma unroll
        for (int nt = 0; nt < 8; ++nt) {
            tm0 = fmaxf(tm0, fmaxf(sacc[nt][0], sacc[nt][1]));
            tm1 = fmaxf(tm1, fmaxf(sacc[nt][2], sacc[nt][3]));
        }
#pragma unroll
        for (int off = 1; off < 4; off <<= 1) {
            tm0 = fmaxf(tm0, __shfl_xor_sync(0xffffffffu, tm0, off));
            tm1 = fmaxf(tm1, __shfl_xor_sync(0xffffffffu, tm1, off));
        }
        const float mn0 = fmaxf(m0, tm0);
        const float mn1 = fmaxf(m1, tm1);
        const float corr0 = ex2f(m0 - mn0);
        const float corr1 = ex2f(m1 - mn1);
        m0 = mn0; m1 = mn1;

        float rs0 = 0.0f, rs1 = 0.0f;
#pragma unroll
        for (int nt = 0; nt < 8; ++nt) {
            float p0 = ex2f(sacc[nt][0] - mn0);
            float p1 = ex2f(sacc[nt][1] - mn0);
            float p2 = ex2f(sacc[nt][2] - mn1);
            float p3 = ex2f(sacc[nt][3] - mn1);
            sacc[nt][0] = p0; sacc[nt][1] = p1; sacc[nt][2] = p2; sacc[nt][3] = p3;
            rs0 += p0 + p1;
            rs1 += p2 + p3;
#pragma unroll
            for (int q = 0; q < 2; ++q) { oacc[nt][q] *= corr0; oacc[nt][q + 2] *= corr1; }
        }
        l0 = l0 * corr0 + rs0;     // per-lane partial (no shfl)
        l1 = l1 * corr1 + rs1;

        // ---- O += P V : P C-frags ARE the f16 A-frags (no transpose!) ----
#pragma unroll
        for (int s = 0; s < 4; ++s) {          // k16-step over keys
            uint32_t a[4];
            a[0] = packh2(sacc[2 * s][0],     sacc[2 * s][1]);
            a[1] = packh2(sacc[2 * s][2],     sacc[2 * s][3]);
            a[2] = packh2(sacc[2 * s + 1][0], sacc[2 * s + 1][1]);
            a[3] = packh2(sacc[2 * s + 1][2], sacc[2 * s + 1][3]);
#pragma unroll
            for (int nt = 0; nt < 8; ++nt) {
                uint32_t bb[2];
                bb[0] = Vs[(nt * 8 + g) * FA_STR + s * 8 + t];
                bb[1] = Vs[(nt * 8 + g) * FA_STR + s * 8 + 4 + t];
                mma16n8k16h(oacc[nt], a, bb);
            }
        }
    }

    // ---- epilogue: reduce l across quad, normalize, write f16 ----
#pragma unroll
    for (int off = 1; off < 4; off <<= 1) {
        l0 += __shfl_xor_sync(0xffffffffu, l0, off);
        l1 += __shfl_xor_sync(0xffffffffu, l1, off);
    }
    const float rl0 = 1.0f / l0;
    const float rl1 = 1.0f / l1;
    const size_t row0 = (size_t)(b * T_ + q0 + qr + g);
    const size_t row1 = row0 + 8;
#pragma unroll
    for (int nt = 0; nt < 8; ++nt) {
        const int col = h * HD_ + nt * 8 + 2 * t;
        *(uint32_t*)(g_yh + row0 * C_ + col) = packh2(oacc[nt][0] * rl0, oacc[nt][1] * rl0);
        *(uint32_t*)(g_yh + row1 * C_ + col) = packh2(oacc[nt][2] * rl1, oacc[nt][3] * rl1);
    }
}

// ============================================================================
// launch
// ============================================================================
extern "C" void kernel_launch(void* const* d_in, const int* in_sizes, int n_in,
                              void* d_out, int out_size)
{
    const float* x      = (const float*)d_in[0];
    const float* w_attn = (const float*)d_in[1];
    const float* w_proj = (const float*)d_in[2];
    float* out = (float*)d_out;

    float* qkv_ptr; cudaGetSymbolAddress((void**)&qkv_ptr, g_qkv);
    __half* yh;     cudaGetSymbolAddress((void**)&yh,  g_yh);
    __half* xh;     cudaGetSymbolAddress((void**)&xh,  g_xh);
    __half* wah;    cudaGetSymbolAddress((void**)&wah, g_wah);
    __half* wph;    cudaGetSymbolAddress((void**)&wph, g_wph);

    cudaFuncSetAttribute(flash_tc, cudaFuncAttributeMaxDynamicSharedMemorySize, FLASH_SMEM);
    cudaFuncSetAttribute(gemm_f16, cudaFuncAttributeMaxDynamicSharedMemorySize, GEMM_SMEM);

    // 0) convert inputs to f16; build rope table
    {
        int nx = M_ROWS * C_;
        to_f16<<<(nx / 8 + 255) / 256, 256>>>(x, xh, nx);
        int na = QKV_N * C_;
        to_f16<<<(na / 8 + 255) / 256, 256>>>(w_attn, wah, na);
        int np = C_ * C_;
        to_f16<<<(np / 8 + 255) / 256, 256>>>(w_proj, wph, np);
        rope_tab<<<(T_ * 32 + 255) / 256, 256>>>();
    }

    // 1) QKV = x @ w_attn^T : (8192, 3072), f16 tensor cores
    gemm_f16<<<dim3(QKV_N / 128, M_ROWS / 128), 256, GEMM_SMEM>>>(
        xh, wah, qkv_ptr, M_ROWS, QKV_N, C_);

    // 2) RoPE + rearrange -> f16 Q/K (natural), V transposed
    {
        int n = B_ * T_ * H_ * (HD_ / 2);
        rope_rearrange<<<(n + 255) / 256, 256>>>(qkv_ptr);
    }

    // 3) flash attention (f16 mma) -> g_yh
    flash_tc<<<dim3(T_ / 128, B_ * H_), 256, FLASH_SMEM>>>();

    // 4) out = y @ w_proj^T : (8192, 1024), f16 tensor cores
    gemm_f16<<<dim3(C_ / 128, M_ROWS / 128), 256, GEMM_SMEM>>>(
        yh, wph, out, M_ROWS, C_, C_);
}

// round 16
// speedup vs baseline: 1.9977x; 1.0058x over previous
#include <cuda_runtime.h>
#include <cuda_fp16.h>
#include <math.h>
#include <cstdint>

// Problem constants (fixed shapes from reference)
#define B_  4
#define T_  2048
#define C_  1024
#define H_  16
#define HD_ 64
#define M_ROWS (B_ * T_)          // 8192
#define QKV_N  (3 * C_)           // 3072

// -------- scratch (device globals; no allocation allowed) --------
__device__ __half   g_qkvh[(size_t)M_ROWS * QKV_N];    // f16 (B*T, 3C)
__device__ __half   g_qh[(size_t)B_ * H_ * T_ * HD_];  // f16, roped, *0.125*log2e
__device__ __half   g_kh[(size_t)B_ * H_ * T_ * HD_];  // f16, roped
__device__ __half   g_vt[(size_t)B_ * H_ * HD_ * T_];  // f16, V TRANSPOSED (bh, d, t)
__device__ __half   g_yh[(size_t)M_ROWS * C_];         // f16 (B, T, C) attention out
__device__ __half   g_xh[(size_t)M_ROWS * C_];         // f16(x)
__device__ __half   g_wah[(size_t)QKV_N * C_];         // f16(w_attn)
__device__ __half   g_wph[(size_t)C_ * C_];            // f16(w_proj)
__device__ float2   g_rt[(size_t)T_ * 32];             // rope cos/sin table

// ---- helpers ----
__device__ __forceinline__ float ex2f(float x) {
    float r; asm("ex2.approx.ftz.f32 %0, %1;" : "=f"(r) : "f"(x)); return r;
}
// f16: D(16x8) += A(16x16) B(16x8), fp32 accum
__device__ __forceinline__ void mma16n8k16h(float c[4], const uint32_t a[4], const uint32_t b[2]) {
    asm volatile(
        "mma.sync.aligned.m16n8k16.row.col.f32.f16.f16.f32 "
        "{%0,%1,%2,%3}, {%4,%5,%6,%7}, {%8,%9}, {%0,%1,%2,%3};"
        : "+f"(c[0]), "+f"(c[1]), "+f"(c[2]), "+f"(c[3])
        : "r"(a[0]), "r"(a[1]), "r"(a[2]), "r"(a[3]), "r"(b[0]), "r"(b[1]));
}
__device__ __forceinline__ uint32_t smem_u32(const void* p) {
    uint32_t a;
    asm("{ .reg .u64 t; cvta.to.shared.u64 t, %1; cvt.u32.u64 %0, t; }" : "=r"(a) : "l"(p));
    return a;
}
__device__ __forceinline__ void cp16(uint32_t dst, const void* src) {
    asm volatile("cp.async.cg.shared.global [%0], [%1], 16;" :: "r"(dst), "l"(src));
}
__device__ __forceinline__ uint32_t packh2(float lo, float hi) {
    __half2 h = __floats2half2_rn(lo, hi);
    return *(uint32_t*)&h;
}
#define CP_COMMIT() asm volatile("cp.async.commit_group;" ::: "memory")
#define CP_WAIT1()  asm volatile("cp.async.wait_group 1;" ::: "memory")
#define CP_WAIT0()  asm volatile("cp.async.wait_group 0;" ::: "memory")

// ============================================================================
// prep: ALL input conversions + fp64 rope table in ONE launch.
// Block partition: [0,4096) x -> xh; [4096,5632) w_attn; [5632,6144) w_proj;
// [6144,6400) rope table. fp64-bound table blocks overlap mem-bound converts.
// ============================================================================
#define PREP_BLOCKS 6400

__global__ __launch_bounds__(256) void prep(const float* __restrict__ x,
                                            const float* __restrict__ wa,
                                            const float* __restrict__ wp)
{
    const int bid = blockIdx.x;
    if (bid < 6144) {
        const float* in;
        __half* out;
        int base;
        if (bid < 4096)      { in = x;  out = g_xh;  base = bid; }
        else if (bid < 5632) { in = wa; out = g_wah; base = bid - 4096; }
        else                 { in = wp; out = g_wph; base = bid - 5632; }
        int i = (base * 256 + threadIdx.x) * 8;
        float4 v0 = *(const float4*)(in + i);
        float4 v1 = *(const float4*)(in + i + 4);
        uint4 o;
        o.x = packh2(v0.x, v0.y); o.y = packh2(v0.z, v0.w);
        o.z = packh2(v1.x, v1.y); o.w = packh2(v1.z, v1.w);
        *(uint4*)(out + i) = o;
    } else {
        int idx = (bid - 6144) * 256 + threadIdx.x;   // < 65536
        int i = idx & 31;
        int t = idx >> 5;
        double inv = exp2(-(double)i * (13.287712379549449595 / 32.0)); // 10000^(-i/32)
        double ds, dc;
        sincos((double)t * inv, &ds, &dc);
        g_rt[idx] = make_float2((float)dc, (float)ds);
    }
}

// ============================================================================
// FP16 tensor-core GEMM (NT), templated output (fp32 or f16 epilogue).
// Mainloop identical to the Round-14/15 passing version.
// ============================================================================
#define GEMM_SMEM (24576 * 4)    // 3 stages x (A 4096 + B 4096) words = 96KB

template <typename OutT>
__global__ void __launch_bounds__(256, 2) gemm_f16(
    const __half* __restrict__ A, const __half* __restrict__ Bm,
    OutT* __restrict__ C, int M, int N, int K)
{
    extern __shared__ uint32_t sm[];
    const uint32_t sbase = smem_u32(sm);

    const int tid  = threadIdx.x;
    const int lane = tid & 31;
    const int wid  = tid >> 5;
    const int wm = wid & 1;
    const int wn = wid >> 1;
    const int g = lane >> 2;
    const int t = lane & 3;
    const int bm = blockIdx.y * 128;
    const int bn = blockIdx.x * 128;

    const int lrow = tid >> 3;       // 0..31 (+p*32)
    const int lu   = tid & 7;        // 16B unit (8 halves)

    float acc[4][4][4];
#pragma unroll
    for (int mt = 0; mt < 4; ++mt)
#pragma unroll
        for (int nt = 0; nt < 4; ++nt)
#pragma unroll
            for (int q = 0; q < 4; ++q) acc[mt][nt][q] = 0.0f;

    auto cp_tile = [&](int k0, int s) {
#pragma unroll
        for (int p = 0; p < 4; ++p) {
            int row = lrow + p * 32;
            int u = lu ^ (row & 7);
            cp16(sbase + (uint32_t)(s * 4096 + row * 32 + u * 4) * 4,
                 A + (size_t)(bm + row) * K + k0 + lu * 8);
            cp16(sbase + (uint32_t)(12288 + s * 4096 + row * 32 + u * 4) * 4,
                 Bm + (size_t)(bn + row) * K + k0 + lu * 8);
        }
    };

    const int nk = K >> 6;           // BK = 64 halves
    cp_tile(0, 0); CP_COMMIT();
    cp_tile(64, 1); CP_COMMIT();

    for (int kt = 0; kt < nk; ++kt) {
        if (kt + 1 < nk) CP_WAIT1(); else CP_WAIT0();
        __syncthreads();

        const int cs = kt % 3;
        const uint32_t* Asb = sm + cs * 4096;
        const uint32_t* Bsb = sm + 12288 + cs * 4096;

#pragma unroll
        for (int s = 0; s < 4; ++s) {            // 4 k16-steps per BK=64
            const int u0 = (2 * s) ^ g;
            const int u1 = u0 ^ 1;

            uint32_t af[4][4];
#pragma unroll
            for (int mt = 0; mt < 4; ++mt) {
                const int r0 = wm * 64 + mt * 16 + g;
                af[mt][0] = Asb[r0 * 32 + u0 * 4 + t];
                af[mt][1] = Asb[(r0 + 8) * 32 + u0 * 4 + t];
                af[mt][2] = Asb[r0 * 32 + u1 * 4 + t];
                af[mt][3] = Asb[(r0 + 8) * 32 + u1 * 4 + t];
            }
            uint32_t bf[4][2];
#pragma unroll
            for (int nt = 0; nt < 4; ++nt) {
                const int n0 = wn * 32 + nt * 8 + g;
                bf[nt][0] = Bsb[n0 * 32 + u0 * 4 + t];
                bf[nt][1] = Bsb[n0 * 32 + u1 * 4 + t];
            }
#pragma unroll
            for (int mt = 0; mt < 4; ++mt)
#pragma unroll
                for (int nt = 0; nt < 4; ++nt)
                    mma16n8k16h(acc[mt][nt], af[mt], bf[nt]);
        }

        if (kt + 2 < nk) {
            cp_tile((kt + 2) << 6, (kt + 2) % 3);
            CP_COMMIT();
        }
    }

#pragma unroll
    for (int mt = 0; mt < 4; ++mt) {
        const int row = bm + wm * 64 + mt * 16 + g;
#pragma unroll
        for (int nt = 0; nt < 4; ++nt) {
            const int col = bn + wn * 32 + nt * 8 + 2 * t;
            if constexpr (sizeof(OutT) == 4) {
                *(float2*)(C + (size_t)row * N + col)       = make_float2(acc[mt][nt][0], acc[mt][nt][1]);
                *(float2*)(C + (size_t)(row + 8) * N + col) = make_float2(acc[mt][nt][2], acc[mt][nt][3]);
            } else {
                *(uint32_t*)(C + (size_t)row * N + col)       = packh2(acc[mt][nt][0], acc[mt][nt][1]);
                *(uint32_t*)(C + (size_t)(row + 8) * N + col) = packh2(acc[mt][nt][2], acc[mt][nt][3]);
            }
        }
    }
}

// ============================================================================
// RoPE + rearrange: qkv (f16) -> Q/K f16 (roped; Q *0.125*log2e), V f16
// TRANSPOSED to (bh, d, t). V path is exact (f16 passthrough).
// ============================================================================
__global__ __launch_bounds__(256) void rope_rearrange()
{
    int idx = blockIdx.x * blockDim.x + threadIdx.x;
    if (idx >= B_ * T_ * H_ * (HD_ / 2)) return;

    int i = idx & 31;               // pair index 0..31
    int h = (idx >> 5) & 15;
    int t = (idx >> 9) & 2047;
    int b = idx >> 20;

    const __half* src = g_qkvh + (size_t)(b * T_ + t) * QKV_N + h * HD_ + 2 * i;

    float2 cs = g_rt[t * 32 + i];
    float c = cs.x, s = cs.y;

    float2 qv = __half22float2(*(const __half2*)(src));
    float2 kv = __half22float2(*(const __half2*)(src + C_));
    __half2 vv = *(const __half2*)(src + 2 * C_);

    const int bh = b * H_ + h;
    size_t dst = ((size_t)bh * T_ + t) * HD_ + 2 * i;
    const float qs = 0.125f * 1.44269504088896340736f;  // 1/sqrt(64) * log2(e)
    *(uint32_t*)(g_qh + dst) = packh2((qv.x * c - qv.y * s) * qs, (qv.x * s + qv.y * c) * qs);
    *(uint32_t*)(g_kh + dst) = packh2(kv.x * c - kv.y * s, kv.x * s + kv.y * c);

    // V transposed: g_vt[bh][d][t] (exact f16 copy)
    size_t vbase = ((size_t)bh * HD_ + 2 * i) * T_ + t;
    g_vt[vbase]      = __low2half(vv);
    g_vt[vbase + T_] = __high2half(vv);
}

// ============================================================================
// FP16 tensor-core flash attention v8 — unchanged from Round 15 passing version.
// ============================================================================
#define FA_STR  36                                 // words per row (32 + 4 pad)
#define FA_TSZ  (64 * FA_STR)                      // 2304 words per tile
#define FA_STG  (2 * FA_TSZ)                       // K + V per stage
#define FLASH_SMEM (2 * FA_STG * 4)                // 36864 bytes

__global__ void __launch_bounds__(256, 2) flash_tc()
{
    extern __shared__ uint32_t fsm[];
    const uint32_t sbase = smem_u32(fsm);

    const int bh = blockIdx.y;                // 0..63
    const int b  = bh >> 4;
    const int h  = bh & 15;
    const int q0 = blockIdx.x * 128;

    const __half* Qb  = g_qh + (size_t)bh * T_ * HD_;
    const __half* Kb  = g_kh + (size_t)bh * T_ * HD_;
    const __half* Vtb = g_vt + (size_t)bh * HD_ * T_;

    const int tid  = threadIdx.x;
    const int lane = tid & 31;
    const int wid  = tid >> 5;
    const int g = lane >> 2;       // quad row
    const int t = lane & 3;        // quad col
    const int qr = wid * 16;       // warp's q-row base within tile

    // ---- Q fragments in registers (f16, loop-invariant) ----
    uint32_t qf[4][4];
    {
        const __half* qrow0 = Qb + (size_t)(q0 + qr + g) * HD_;
        const __half* qrow1 = qrow0 + 8 * HD_;
#pragma unroll
        for (int s = 0; s < 4; ++s) {
            qf[s][0] = *(const uint32_t*)(qrow0 + 16 * s + 2 * t);
            qf[s][1] = *(const uint32_t*)(qrow1 + 16 * s + 2 * t);
            qf[s][2] = *(const uint32_t*)(qrow0 + 16 * s + 8 + 2 * t);
            qf[s][3] = *(const uint32_t*)(qrow1 + 16 * s + 8 + 2 * t);
        }
    }

    // cp.async tile loader: K [key][d]; V [d][key]; rows of 64 halves.
    auto cp_kv = [&](int k0, int s) {
        const uint32_t koff = (uint32_t)s * FA_STG;
        const uint32_t voff = koff + FA_TSZ;
#pragma unroll
        for (int p = 0; p < 2; ++p) {
            int idx = tid * 2 + p;
            int row = idx >> 3;          // 0..63
            int ch  = idx & 7;           // 16B chunk (8 halves)
            cp16(sbase + (koff + (uint32_t)row * FA_STR + ch * 4) * 4,
                 Kb + (size_t)(k0 + row) * HD_ + ch * 8);
            cp16(sbase + (voff + (uint32_t)row * FA_STR + ch * 4) * 4,
                 Vtb + (size_t)row * T_ + k0 + ch * 8);
        }
    };

    // online softmax state (rows qr+g, qr+g+8) in log2 domain; per-lane l.
    float m0 = -3.0e38f, m1 = -3.0e38f, l0 = 0.0f, l1 = 0.0f;
    float oacc[8][4];
#pragma unroll
    for (int nt = 0; nt < 8; ++nt)
#pragma unroll
        for (int q = 0; q < 4; ++q) oacc[nt][q] = 0.0f;

    const int NT = T_ / 64;
    cp_kv(0, 0); CP_COMMIT();

    for (int kt = 0; kt < NT; ++kt) {
        CP_WAIT0();
        __syncthreads();
        if (kt + 1 < NT) {
            cp_kv((kt + 1) * 64, (kt + 1) & 1);
            CP_COMMIT();
        }

        const int cs = kt & 1;
        const uint32_t* Ks = fsm + cs * FA_STG;
        const uint32_t* Vs = fsm + cs * FA_STG + FA_TSZ;

        // ---- S = Q K^T (log2 domain): 4 k16-steps x 8 key-blocks ----
        float sacc[8][4];
#pragma unroll
        for (int nt = 0; nt < 8; ++nt)
#pragma unroll
            for (int q = 0; q < 4; ++q) sacc[nt][q] = 0.0f;

#pragma unroll
        for (int s = 0; s < 4; ++s) {
#pragma unroll
            for (int nt = 0; nt < 8; ++nt) {
                uint32_t bb[2];
                bb[0] = Ks[(nt * 8 + g) * FA_STR + s * 8 + t];
                bb[1] = Ks[(nt * 8 + g) * FA_STR + s * 8 + 4 + t];
                mma16n8k16h(sacc[nt], qf[s], bb);
            }
        }

        // ---- online softmax (exp2 domain; only MAX needs quad reduce) ----
        float tm0 = -3.0e38f, tm1 = -3.0e38f;
#pragma unroll
        for (int nt = 0; nt < 8; ++nt) {
            tm0 = fmaxf(tm0, fmaxf(sacc[nt][0], sacc[nt][1]));
            tm1 = fmaxf(tm1, fmaxf(sacc[nt][2], sacc[nt][3]));
        }
#pragma unroll
        for (int off = 1; off < 4; off <<= 1) {
            tm0 = fmaxf(tm0, __shfl_xor_sync(0xffffffffu, tm0, off));
            tm1 = fmaxf(tm1, __shfl_xor_sync(0xffffffffu, tm1, off));
        }
        const float mn0 = fmaxf(m0, tm0);
        const float mn1 = fmaxf(m1, tm1);
        const float corr0 = ex2f(m0 - mn0);
        const float corr1 = ex2f(m1 - mn1);
        m0 = mn0; m1 = mn1;

        float rs0 = 0.0f, rs1 = 0.0f;
#pragma unroll
        for (int nt = 0; nt < 8; ++nt) {
            float p0 = ex2f(sacc[nt][0] - mn0);
            float p1 = ex2f(sacc[nt][1] - mn0);
            float p2 = ex2f(sacc[nt][2] - mn1);
            float p3 = ex2f(sacc[nt][3] - mn1);
            sacc[nt][0] = p0; sacc[nt][1] = p1; sacc[nt][2] = p2; sacc[nt][3] = p3;
            rs0 += p0 + p1;
            rs1 += p2 + p3;
#pragma unroll
            for (int q = 0; q < 2; ++q) { oacc[nt][q] *= corr0; oacc[nt][q + 2] *= corr1; }
        }
        l0 = l0 * corr0 + rs0;     // per-lane partial (no shfl)
        l1 = l1 * corr1 + rs1;

        // ---- O += P V : P C-frags ARE the f16 A-frags (no transpose) ----
#pragma unroll
        for (int s = 0; s < 4; ++s) {          // k16-step over keys
            uint32_t a[4];
            a[0] = packh2(sacc[2 * s][0],     sacc[2 * s][1]);
            a[1] = packh2(sacc[2 * s][2],     sacc[2 * s][3]);
            a[2] = packh2(sacc[2 * s + 1][0], sacc[2 * s + 1][1]);
            a[3] = packh2(sacc[2 * s + 1][2], sacc[2 * s + 1][3]);
#pragma unroll
            for (int nt = 0; nt < 8; ++nt) {
                uint32_t bb[2];
                bb[0] = Vs[(nt * 8 + g) * FA_STR + s * 8 + t];
                bb[1] = Vs[(nt * 8 + g) * FA_STR + s * 8 + 4 + t];
                mma16n8k16h(oacc[nt], a, bb);
            }
        }
    }

    // ---- epilogue: reduce l across quad, normalize, write f16 ----
#pragma unroll
    for (int off = 1; off < 4; off <<= 1) {
        l0 += __shfl_xor_sync(0xffffffffu, l0, off);
        l1 += __shfl_xor_sync(0xffffffffu, l1, off);
    }
    const float rl0 = 1.0f / l0;
    const float rl1 = 1.0f / l1;
    const size_t row0 = (size_t)(b * T_ + q0 + qr + g);
    const size_t row1 = row0 + 8;
#pragma unroll
    for (int nt = 0; nt < 8; ++nt) {
        const int col = h * HD_ + nt * 8 + 2 * t;
        *(uint32_t*)(g_yh + row0 * C_ + col) = packh2(oacc[nt][0] * rl0, oacc[nt][1] * rl0);
        *(uint32_t*)(g_yh + row1 * C_ + col) = packh2(oacc[nt][2] * rl1, oacc[nt][3] * rl1);
    }
}

// ============================================================================
// launch
// ============================================================================
extern "C" void kernel_launch(void* const* d_in, const int* in_sizes, int n_in,
                              void* d_out, int out_size)
{
    const float* x      = (const float*)d_in[0];
    const float* w_attn = (const float*)d_in[1];
    const float* w_proj = (const float*)d_in[2];
    float* out = (float*)d_out;

    __half* qkvh;   cudaGetSymbolAddress((void**)&qkvh, g_qkvh);
    __half* yh;     cudaGetSymbolAddress((void**)&yh,  g_yh);
    __half* xh;     cudaGetSymbolAddress((void**)&xh,  g_xh);
    __half* wah;    cudaGetSymbolAddress((void**)&wah, g_wah);
    __half* wph;    cudaGetSymbolAddress((void**)&wph, g_wph);

    cudaFuncSetAttribute(flash_tc, cudaFuncAttributeMaxDynamicSharedMemorySize, FLASH_SMEM);
    cudaFuncSetAttribute(gemm_f16<float>,  cudaFuncAttributeMaxDynamicSharedMemorySize, GEMM_SMEM);
    cudaFuncSetAttribute(gemm_f16<__half>, cudaFuncAttributeMaxDynamicSharedMemorySize, GEMM_SMEM);

    // 0) all conversions + rope table, one launch
    prep<<<PREP_BLOCKS, 256>>>(x, w_attn, w_proj);

    // 1) QKV = x @ w_attn^T : (8192, 3072), f16 in / f16 out
    gemm_f16<__half><<<dim3(QKV_N / 128, M_ROWS / 128), 256, GEMM_SMEM>>>(
        xh, wah, qkvh, M_ROWS, QKV_N, C_);

    // 2) RoPE + rearrange -> f16 Q/K (natural), V transposed
    {
        int n = B_ * T_ * H_ * (HD_ / 2);
        rope_rearrange<<<(n + 255) / 256, 256>>>();
    }

    // 3) flash attention (f16 mma) -> g_yh
    flash_tc<<<dim3(T_ / 128, B_ * H_), 256, FLASH_SMEM>>>();

    // 4) out = y @ w_proj^T : (8192, 1024), fp32 out
    gemm_f16<float><<<dim3(C_ / 128, M_ROWS / 128), 256, GEMM_SMEM>>>(
        yh, wph, out, M_ROWS, C_, C_);
}

// round 17
// speedup vs baseline: 2.0797x; 1.0410x over previous
#include <cuda_runtime.h>
#include <cuda_fp16.h>
#include <math.h>
#include <cstdint>

// Problem constants (fixed shapes from reference)
#define B_  4
#define T_  2048
#define C_  1024
#define H_  16
#define HD_ 64
#define M_ROWS (B_ * T_)          // 8192
#define QKV_N  (3 * C_)           // 3072

// -------- scratch (device globals; no allocation allowed) --------
__device__ __half   g_qkvh[(size_t)M_ROWS * QKV_N];    // f16 (B*T, 3C)
__device__ __half   g_qh[(size_t)B_ * H_ * T_ * HD_];  // f16, roped, *0.125*log2e
__device__ __half   g_kh[(size_t)B_ * H_ * T_ * HD_];  // f16, roped
__device__ __half   g_vt[(size_t)B_ * H_ * HD_ * T_];  // f16, V TRANSPOSED (bh, d, t)
__device__ __half   g_yh[(size_t)M_ROWS * C_];         // f16 (B, T, C) attention out
__device__ __half   g_xh[(size_t)M_ROWS * C_];         // f16(x)
__device__ __half   g_wah[(size_t)QKV_N * C_];         // f16(w_attn)
__device__ __half   g_wph[(size_t)C_ * C_];            // f16(w_proj)
__device__ float2   g_rt[(size_t)T_ * 32];             // rope cos/sin table

// ---- helpers ----
__device__ __forceinline__ float ex2f(float x) {
    float r; asm("ex2.approx.ftz.f32 %0, %1;" : "=f"(r) : "f"(x)); return r;
}
// f16: D(16x8) += A(16x16) B(16x8), fp32 accum
__device__ __forceinline__ void mma16n8k16h(float c[4], const uint32_t a[4], const uint32_t b[2]) {
    asm volatile(
        "mma.sync.aligned.m16n8k16.row.col.f32.f16.f16.f32 "
        "{%0,%1,%2,%3}, {%4,%5,%6,%7}, {%8,%9}, {%0,%1,%2,%3};"
        : "+f"(c[0]), "+f"(c[1]), "+f"(c[2]), "+f"(c[3])
        : "r"(a[0]), "r"(a[1]), "r"(a[2]), "r"(a[3]), "r"(b[0]), "r"(b[1]));
}
// ldmatrix x4: lane l supplies row address for matrix l>>3, row l&7
__device__ __forceinline__ void ldsm_x4(uint32_t& r0, uint32_t& r1, uint32_t& r2, uint32_t& r3,
                                        uint32_t addr) {
    asm volatile("ldmatrix.sync.aligned.m8n8.x4.shared.b16 {%0,%1,%2,%3}, [%4];"
                 : "=r"(r0), "=r"(r1), "=r"(r2), "=r"(r3) : "r"(addr));
}
__device__ __forceinline__ uint32_t smem_u32(const void* p) {
    uint32_t a;
    asm("{ .reg .u64 t; cvta.to.shared.u64 t, %1; cvt.u32.u64 %0, t; }" : "=r"(a) : "l"(p));
    return a;
}
__device__ __forceinline__ void cp16(uint32_t dst, const void* src) {
    asm volatile("cp.async.cg.shared.global [%0], [%1], 16;" :: "r"(dst), "l"(src));
}
__device__ __forceinline__ uint32_t packh2(float lo, float hi) {
    __half2 h = __floats2half2_rn(lo, hi);
    return *(uint32_t*)&h;
}
#define CP_COMMIT() asm volatile("cp.async.commit_group;" ::: "memory")
#define CP_WAIT1()  asm volatile("cp.async.wait_group 1;" ::: "memory")
#define CP_WAIT0()  asm volatile("cp.async.wait_group 0;" ::: "memory")

// ============================================================================
// prep: ALL input conversions + fp64 rope table in ONE launch.
// ============================================================================
#define PREP_BLOCKS 6400

__global__ __launch_bounds__(256) void prep(const float* __restrict__ x,
                                            const float* __restrict__ wa,
                                            const float* __restrict__ wp)
{
    const int bid = blockIdx.x;
    if (bid < 6144) {
        const float* in;
        __half* out;
        int base;
        if (bid < 4096)      { in = x;  out = g_xh;  base = bid; }
        else if (bid < 5632) { in = wa; out = g_wah; base = bid - 4096; }
        else                 { in = wp; out = g_wph; base = bid - 5632; }
        int i = (base * 256 + threadIdx.x) * 8;
        float4 v0 = *(const float4*)(in + i);
        float4 v1 = *(const float4*)(in + i + 4);
        uint4 o;
        o.x = packh2(v0.x, v0.y); o.y = packh2(v0.z, v0.w);
        o.z = packh2(v1.x, v1.y); o.w = packh2(v1.z, v1.w);
        *(uint4*)(out + i) = o;
    } else {
        int idx = (bid - 6144) * 256 + threadIdx.x;   // < 65536
        int i = idx & 31;
        int t = idx >> 5;
        double inv = exp2(-(double)i * (13.287712379549449595 / 32.0)); // 10000^(-i/32)
        double ds, dc;
        sincos((double)t * inv, &ds, &dc);
        g_rt[idx] = make_float2((float)dc, (float)ds);
    }
}

// ============================================================================
// FP16 tensor-core GEMM (NT), templated output — unchanged from Round 16.
// ============================================================================
#define GEMM_SMEM (24576 * 4)    // 3 stages x (A 4096 + B 4096) words = 96KB

template <typename OutT>
__global__ void __launch_bounds__(256, 2) gemm_f16(
    const __half* __restrict__ A, const __half* __restrict__ Bm,
    OutT* __restrict__ C, int M, int N, int K)
{
    extern __shared__ uint32_t sm[];
    const uint32_t sbase = smem_u32(sm);

    const int tid  = threadIdx.x;
    const int lane = tid & 31;
    const int wid  = tid >> 5;
    const int wm = wid & 1;
    const int wn = wid >> 1;
    const int g = lane >> 2;
    const int t = lane & 3;
    const int bm = blockIdx.y * 128;
    const int bn = blockIdx.x * 128;

    const int lrow = tid >> 3;       // 0..31 (+p*32)
    const int lu   = tid & 7;        // 16B unit (8 halves)

    float acc[4][4][4];
#pragma unroll
    for (int mt = 0; mt < 4; ++mt)
#pragma unroll
        for (int nt = 0; nt < 4; ++nt)
#pragma unroll
            for (int q = 0; q < 4; ++q) acc[mt][nt][q] = 0.0f;

    auto cp_tile = [&](int k0, int s) {
#pragma unroll
        for (int p = 0; p < 4; ++p) {
            int row = lrow + p * 32;
            int u = lu ^ (row & 7);
            cp16(sbase + (uint32_t)(s * 4096 + row * 32 + u * 4) * 4,
                 A + (size_t)(bm + row) * K + k0 + lu * 8);
            cp16(sbase + (uint32_t)(12288 + s * 4096 + row * 32 + u * 4) * 4,
                 Bm + (size_t)(bn + row) * K + k0 + lu * 8);
        }
    };

    const int nk = K >> 6;           // BK = 64 halves
    cp_tile(0, 0); CP_COMMIT();
    cp_tile(64, 1); CP_COMMIT();

    for (int kt = 0; kt < nk; ++kt) {
        if (kt + 1 < nk) CP_WAIT1(); else CP_WAIT0();
        __syncthreads();

        const int cs = kt % 3;
        const uint32_t* Asb = sm + cs * 4096;
        const uint32_t* Bsb = sm + 12288 + cs * 4096;

#pragma unroll
        for (int s = 0; s < 4; ++s) {            // 4 k16-steps per BK=64
            const int u0 = (2 * s) ^ g;
            const int u1 = u0 ^ 1;

            uint32_t af[4][4];
#pragma unroll
            for (int mt = 0; mt < 4; ++mt) {
                const int r0 = wm * 64 + mt * 16 + g;
                af[mt][0] = Asb[r0 * 32 + u0 * 4 + t];
                af[mt][1] = Asb[(r0 + 8) * 32 + u0 * 4 + t];
                af[mt][2] = Asb[r0 * 32 + u1 * 4 + t];
                af[mt][3] = Asb[(r0 + 8) * 32 + u1 * 4 + t];
            }
            uint32_t bf[4][2];
#pragma unroll
            for (int nt = 0; nt < 4; ++nt) {
                const int n0 = wn * 32 + nt * 8 + g;
                bf[nt][0] = Bsb[n0 * 32 + u0 * 4 + t];
                bf[nt][1] = Bsb[n0 * 32 + u1 * 4 + t];
            }
#pragma unroll
            for (int mt = 0; mt < 4; ++mt)
#pragma unroll
                for (int nt = 0; nt < 4; ++nt)
                    mma16n8k16h(acc[mt][nt], af[mt], bf[nt]);
        }

        if (kt + 2 < nk) {
            cp_tile((kt + 2) << 6, (kt + 2) % 3);
            CP_COMMIT();
        }
    }

#pragma unroll
    for (int mt = 0; mt < 4; ++mt) {
        const int row = bm + wm * 64 + mt * 16 + g;
#pragma unroll
        for (int nt = 0; nt < 4; ++nt) {
            const int col = bn + wn * 32 + nt * 8 + 2 * t;
            if constexpr (sizeof(OutT) == 4) {
                *(float2*)(C + (size_t)row * N + col)       = make_float2(acc[mt][nt][0], acc[mt][nt][1]);
                *(float2*)(C + (size_t)(row + 8) * N + col) = make_float2(acc[mt][nt][2], acc[mt][nt][3]);
            } else {
                *(uint32_t*)(C + (size_t)row * N + col)       = packh2(acc[mt][nt][0], acc[mt][nt][1]);
                *(uint32_t*)(C + (size_t)(row + 8) * N + col) = packh2(acc[mt][nt][2], acc[mt][nt][3]);
            }
        }
    }
}

// ============================================================================
// RoPE + rearrange — unchanged from Round 16.
// ============================================================================
__global__ __launch_bounds__(256) void rope_rearrange()
{
    int idx = blockIdx.x * blockDim.x + threadIdx.x;
    if (idx >= B_ * T_ * H_ * (HD_ / 2)) return;

    int i = idx & 31;               // pair index 0..31
    int h = (idx >> 5) & 15;
    int t = (idx >> 9) & 2047;
    int b = idx >> 20;

    const __half* src = g_qkvh + (size_t)(b * T_ + t) * QKV_N + h * HD_ + 2 * i;

    float2 cs = g_rt[t * 32 + i];
    float c = cs.x, s = cs.y;

    float2 qv = __half22float2(*(const __half2*)(src));
    float2 kv = __half22float2(*(const __half2*)(src + C_));
    __half2 vv = *(const __half2*)(src + 2 * C_);

    const int bh = b * H_ + h;
    size_t dst = ((size_t)bh * T_ + t) * HD_ + 2 * i;
    const float qs = 0.125f * 1.44269504088896340736f;  // 1/sqrt(64) * log2(e)
    *(uint32_t*)(g_qh + dst) = packh2((qv.x * c - qv.y * s) * qs, (qv.x * s + qv.y * c) * qs);
    *(uint32_t*)(g_kh + dst) = packh2(kv.x * c - kv.y * s, kv.x * s + kv.y * c);

    // V transposed: g_vt[bh][d][t] (exact f16 copy)
    size_t vbase = ((size_t)bh * HD_ + 2 * i) * T_ + t;
    g_vt[vbase]      = __low2half(vv);
    g_vt[vbase + T_] = __high2half(vv);
}

// ============================================================================
// FP16 flash attention v9: as v8, but ALL K/V B-fragments loaded with
// ldmatrix.x4 (16 LDSM per warp-tile instead of 128 LDS.32).
// Lane l supplies the row address for matrix l>>3, row l&7:
//   matrix m: nt' = 2j + (m>>1), k-chunk c = m&1
//   addr = tile + ((nt'*8 + r)*FA_STR + s*8 + c*4) words
// ============================================================================
#define FA_STR  36                                 // words per row (32 + 4 pad)
#define FA_TSZ  (64 * FA_STR)                      // 2304 words per tile
#define FA_STG  (2 * FA_TSZ)                       // K + V per stage
#define FLASH_SMEM (2 * FA_STG * 4)                // 36864 bytes

__global__ void __launch_bounds__(256, 2) flash_tc()
{
    extern __shared__ uint32_t fsm[];
    const uint32_t sbase = smem_u32(fsm);

    const int bh = blockIdx.y;                // 0..63
    const int b  = bh >> 4;
    const int h  = bh & 15;
    const int q0 = blockIdx.x * 128;

    const __half* Qb  = g_qh + (size_t)bh * T_ * HD_;
    const __half* Kb  = g_kh + (size_t)bh * T_ * HD_;
    const __half* Vtb = g_vt + (size_t)bh * HD_ * T_;

    const int tid  = threadIdx.x;
    const int lane = tid & 31;
    const int wid  = tid >> 5;
    const int g = lane >> 2;       // quad row
    const int t = lane & 3;        // quad col
    const int qr = wid * 16;       // warp's q-row base within tile

    // ldmatrix lane constants: matrix m = lane>>3, row r = lane&7
    const int lm_m = lane >> 3;
    const int lm_r = lane & 7;
    // byte offset within a tile for (j, s): base_row + j*16 rows + s*8 words
    const uint32_t lm_base = (uint32_t)((((lm_m >> 1) * 8 + lm_r) * FA_STR + (lm_m & 1) * 4) * 4);

    // ---- Q fragments in registers (f16, loop-invariant) ----
    uint32_t qf[4][4];
    {
        const __half* qrow0 = Qb + (size_t)(q0 + qr + g) * HD_;
        const __half* qrow1 = qrow0 + 8 * HD_;
#pragma unroll
        for (int s = 0; s < 4; ++s) {
            qf[s][0] = *(const uint32_t*)(qrow0 + 16 * s + 2 * t);
            qf[s][1] = *(const uint32_t*)(qrow1 + 16 * s + 2 * t);
            qf[s][2] = *(const uint32_t*)(qrow0 + 16 * s + 8 + 2 * t);
            qf[s][3] = *(const uint32_t*)(qrow1 + 16 * s + 8 + 2 * t);
        }
    }

    // cp.async tile loader: K [key][d]; V [d][key]; rows of 64 halves.
    auto cp_kv = [&](int k0, int s) {
        const uint32_t koff = (uint32_t)s * FA_STG;
        const uint32_t voff = koff + FA_TSZ;
#pragma unroll
        for (int p = 0; p < 2; ++p) {
            int idx = tid * 2 + p;
            int row = idx >> 3;          // 0..63
            int ch  = idx & 7;           // 16B chunk (8 halves)
            cp16(sbase + (koff + (uint32_t)row * FA_STR + ch * 4) * 4,
                 Kb + (size_t)(k0 + row) * HD_ + ch * 8);
            cp16(sbase + (voff + (uint32_t)row * FA_STR + ch * 4) * 4,
                 Vtb + (size_t)row * T_ + k0 + ch * 8);
        }
    };

    // online softmax state (rows qr+g, qr+g+8) in log2 domain; per-lane l.
    float m0 = -3.0e38f, m1 = -3.0e38f, l0 = 0.0f, l1 = 0.0f;
    float oacc[8][4];
#pragma unroll
    for (int nt = 0; nt < 8; ++nt)
#pragma unroll
        for (int q = 0; q < 4; ++q) oacc[nt][q] = 0.0f;

    const int NT = T_ / 64;
    cp_kv(0, 0); CP_COMMIT();

    for (int kt = 0; kt < NT; ++kt) {
        CP_WAIT0();
        __syncthreads();
        if (kt + 1 < NT) {
            cp_kv((kt + 1) * 64, (kt + 1) & 1);
            CP_COMMIT();
        }

        const int cs = kt & 1;
        const uint32_t kbase = sbase + (uint32_t)(cs * FA_STG) * 4 + lm_base;
        const uint32_t vbase = kbase + (uint32_t)FA_TSZ * 4;

        // ---- S = Q K^T (log2 domain): K B-frags via ldmatrix.x4 ----
        float sacc[8][4];
#pragma unroll
        for (int nt = 0; nt < 8; ++nt)
#pragma unroll
            for (int q = 0; q < 4; ++q) sacc[nt][q] = 0.0f;

#pragma unroll
        for (int s = 0; s < 4; ++s) {
#pragma unroll
            for (int j = 0; j < 4; ++j) {
                uint32_t b0, b1, b2, b3;
                ldsm_x4(b0, b1, b2, b3,
                        kbase + (uint32_t)((j * 16 * FA_STR + s * 8) * 4));
                uint32_t bb0[2] = {b0, b1};
                uint32_t bb1[2] = {b2, b3};
                mma16n8k16h(sacc[2 * j],     qf[s], bb0);
                mma16n8k16h(sacc[2 * j + 1], qf[s], bb1);
            }
        }

        // ---- online softmax (exp2 domain; only MAX needs quad reduce) ----
        float tm0 = -3.0e38f, tm1 = -3.0e38f;
#pragma unroll
        for (int nt = 0; nt < 8; ++nt) {
            tm0 = fmaxf(tm0, fmaxf(sacc[nt][0], sacc[nt][1]));
            tm1 = fmaxf(tm1, fmaxf(sacc[nt][2], sacc[nt][3]));
        }
#pragma unroll
        for (int off = 1; off < 4; off <<= 1) {
            tm0 = fmaxf(tm0, __shfl_xor_sync(0xffffffffu, tm0, off));
            tm1 = fmaxf(tm1, __shfl_xor_sync(0xffffffffu, tm1, off));
        }
        const float mn0 = fmaxf(m0, tm0);
        const float mn1 = fmaxf(m1, tm1);
        const float corr0 = ex2f(m0 - mn0);
        const float corr1 = ex2f(m1 - mn1);
        m0 = mn0; m1 = mn1;

        float rs0 = 0.0f, rs1 = 0.0f;
#pragma unroll
        for (int nt = 0; nt < 8; ++nt) {
            float p0 = ex2f(sacc[nt][0] - mn0);
            float p1 = ex2f(sacc[nt][1] - mn0);
            float p2 = ex2f(sacc[nt][2] - mn1);
            float p3 = ex2f(sacc[nt][3] - mn1);
            sacc[nt][0] = p0; sacc[nt][1] = p1; sacc[nt][2] = p2; sacc[nt][3] = p3;
            rs0 += p0 + p1;
            rs1 += p2 + p3;
#pragma unroll
            for (int q = 0; q < 2; ++q) { oacc[nt][q] *= corr0; oacc[nt][q + 2] *= corr1; }
        }
        l0 = l0 * corr0 + rs0;     // per-lane partial (no shfl)
        l1 = l1 * corr1 + rs1;

        // ---- O += P V : P C-frags are the f16 A-frags; V via ldmatrix.x4 ----
#pragma unroll
        for (int s = 0; s < 4; ++s) {          // k16-step over keys
            uint32_t a[4];
            a[0] = packh2(sacc[2 * s][0],     sacc[2 * s][1]);
            a[1] = packh2(sacc[2 * s][2],     sacc[2 * s][3]);
            a[2] = packh2(sacc[2 * s + 1][0], sacc[2 * s + 1][1]);
            a[3] = packh2(sacc[2 * s + 1][2], sacc[2 * s + 1][3]);
#pragma unroll
            for (int j = 0; j < 4; ++j) {
                uint32_t b0, b1, b2, b3;
                ldsm_x4(b0, b1, b2, b3,
                        vbase + (uint32_t)((j * 16 * FA_STR + s * 8) * 4));
                uint32_t bb0[2] = {b0, b1};
                uint32_t bb1[2] = {b2, b3};
                mma16n8k16h(oacc[2 * j],     a, bb0);
                mma16n8k16h(oacc[2 * j + 1], a, bb1);
            }
        }
    }

    // ---- epilogue: reduce l across quad, normalize, write f16 ----
#pragma unroll
    for (int off = 1; off < 4; off <<= 1) {
        l0 += __shfl_xor_sync(0xffffffffu, l0, off);
        l1 += __shfl_xor_sync(0xffffffffu, l1, off);
    }
    const float rl0 = 1.0f / l0;
    const float rl1 = 1.0f / l1;
    const size_t row0 = (size_t)(b * T_ + q0 + qr + g);
    const size_t row1 = row0 + 8;
#pragma unroll
    for (int nt = 0; nt < 8; ++nt) {
        const int col = h * HD_ + nt * 8 + 2 * t;
        *(uint32_t*)(g_yh + row0 * C_ + col) = packh2(oacc[nt][0] * rl0, oacc[nt][1] * rl0);
        *(uint32_t*)(g_yh + row1 * C_ + col) = packh2(oacc[nt][2] * rl1, oacc[nt][3] * rl1);
    }
}

// ============================================================================
// launch
// ============================================================================
extern "C" void kernel_launch(void* const* d_in, const int* in_sizes, int n_in,
                              void* d_out, int out_size)
{
    const float* x      = (const float*)d_in[0];
    const float* w_attn = (const float*)d_in[1];
    const float* w_proj = (const float*)d_in[2];
    float* out = (float*)d_out;

    __half* qkvh;   cudaGetSymbolAddress((void**)&qkvh, g_qkvh);
    __half* yh;     cudaGetSymbolAddress((void**)&yh,  g_yh);
    __half* xh;     cudaGetSymbolAddress((void**)&xh,  g_xh);
    __half* wah;    cudaGetSymbolAddress((void**)&wah, g_wah);
    __half* wph;    cudaGetSymbolAddress((void**)&wph, g_wph);

    cudaFuncSetAttribute(flash_tc, cudaFuncAttributeMaxDynamicSharedMemorySize, FLASH_SMEM);
    cudaFuncSetAttribute(gemm_f16<float>,  cudaFuncAttributeMaxDynamicSharedMemorySize, GEMM_SMEM);
    cudaFuncSetAttribute(gemm_f16<__half>, cudaFuncAttributeMaxDynamicSharedMemorySize, GEMM_SMEM);

    // 0) all conversions + rope table, one launch
    prep<<<PREP_BLOCKS, 256>>>(x, w_attn, w_proj);

    // 1) QKV = x @ w_attn^T : (8192, 3072), f16 in / f16 out
    gemm_f16<__half><<<dim3(QKV_N / 128, M_ROWS / 128), 256, GEMM_SMEM>>>(
        xh, wah, qkvh, M_ROWS, QKV_N, C_);

    // 2) RoPE + rearrange -> f16 Q/K (natural), V transposed
    {
        int n = B_ * T_ * H_ * (HD_ / 2);
        rope_rearrange<<<(n + 255) / 256, 256>>>();
    }

    // 3) flash attention (f16 mma + ldmatrix) -> g_yh
    flash_tc<<<dim3(T_ / 128, B_ * H_), 256, FLASH_SMEM>>>();

    // 4) out = y @ w_proj^T : (8192, 1024), fp32 out
    gemm_f16<float><<<dim3(C_ / 128, M_ROWS / 128), 256, GEMM_SMEM>>>(
        yh, wph, out, M_ROWS, C_, C_);
}